// round 11
// baseline (speedup 1.0000x reference)
#include <cuda_runtime.h>
#include <cuda_fp16.h>
#include <math.h>
#include <stdint.h>

#define NH    12
#define HD    128
#define DIM   1536
#define BB    2
#define S_IN  2048
#define S_CTX 256
#define NT    (S_IN + S_CTX)   // 2304
#define Q3    (3 * DIM)        // 4608
#define NKT   (NT / 64)        // 36

// ------------------------- scratch (no cudaMalloc allowed) -------------------
static __device__ __half g_qkv_in [(size_t)BB * S_IN  * Q3];
static __device__ __half g_qkv_ctx[(size_t)BB * S_CTX * Q3];
static __device__ __half g_q[(size_t)BB * NH * NT * HD];   // scaled, [b][h][n][d]
static __device__ __half g_k[(size_t)BB * NH * NT * HD];   // [b][h][n][d]
static __device__ __half g_v[(size_t)BB * NH * NT * HD];   // [b][h][n][d]
static __device__ __half g_o[(size_t)BB * NT * DIM];
static __device__ __half g_wt[18874368];                   // transposed weights
static __device__ __half g_in_r [(size_t)BB * S_IN  * DIM];
static __device__ __half g_ctx_r[(size_t)BB * S_CTX * DIM];
static __device__ float2 g_rope[(size_t)NT * 64];          // (cos, sin)

#define WT_QKV_IN  0
#define WT_QKV_CTX 7077888
#define WT_OUT_IN  14155776
#define WT_OUT_CTX 16515072

// ------------------------- helpers -------------------------------------------
__device__ __forceinline__ unsigned smem_u32(const void* p) {
    unsigned a;
    asm("{ .reg .u64 t; cvta.to.shared.u64 t, %1; cvt.u32.u64 %0, t; }"
        : "=r"(a) : "l"(p));
    return a;
}

__device__ __forceinline__ void cp16(unsigned s, const void* g) {
    unsigned long long ga;
    asm("cvta.to.global.u64 %0, %1;" : "=l"(ga) : "l"(g));
    asm volatile("cp.async.cg.shared.global [%0], [%1], 16;"
                 :: "r"(s), "l"(ga));
}
#define CP_COMMIT() asm volatile("cp.async.commit_group;" ::: "memory")
#define CP_WAIT0()  asm volatile("cp.async.wait_group 0;" ::: "memory")
#define CP_WAIT1()  asm volatile("cp.async.wait_group 1;" ::: "memory")
#define CP_WAIT2()  asm volatile("cp.async.wait_group 2;" ::: "memory")

__device__ __forceinline__ void ldsm4(unsigned* r, unsigned addr) {
    asm volatile("ldmatrix.sync.aligned.m8n8.x4.shared.b16 {%0,%1,%2,%3}, [%4];"
        : "=r"(r[0]), "=r"(r[1]), "=r"(r[2]), "=r"(r[3]) : "r"(addr));
}

__device__ __forceinline__ void ldsm4t(unsigned* r, unsigned addr) {
    asm volatile("ldmatrix.sync.aligned.m8n8.x4.trans.shared.b16 {%0,%1,%2,%3}, [%4];"
        : "=r"(r[0]), "=r"(r[1]), "=r"(r[2]), "=r"(r[3]) : "r"(addr));
}

__device__ __forceinline__ void mma16(float* c, const unsigned* a,
                                      unsigned b0, unsigned b1) {
    asm volatile(
        "mma.sync.aligned.m16n8k16.row.col.f32.f16.f16.f32 "
        "{%0,%1,%2,%3}, {%4,%5,%6,%7}, {%8,%9}, {%0,%1,%2,%3};"
        : "+f"(c[0]), "+f"(c[1]), "+f"(c[2]), "+f"(c[3])
        : "r"(a[0]), "r"(a[1]), "r"(a[2]), "r"(a[3]), "r"(b0), "r"(b1));
}

__device__ __forceinline__ float fexp(float x) {
    float r;
    asm("ex2.approx.ftz.f32 %0, %1;" : "=f"(r) : "f"(x * 1.4426950408889634f));
    return r;
}

// ------------------------- one-shot RoPE table -------------------------------
__global__ void __launch_bounds__(64)
rope_table(void)
{
    int pos = blockIdx.x;
    int t   = threadIdx.x;
    double ang = (double)pos * pow(10000.0, -(double)t / 64.0);
    g_rope[(size_t)pos * 64 + t] = make_float2((float)cos(ang), (float)sin(ang));
}

// ------------------------- merged prep kernels -------------------------------
__global__ void __launch_bounds__(256)
half_copy2(const float* __restrict__ in0, __half* __restrict__ out0, int n40,
           const float* __restrict__ in1, __half* __restrict__ out1, int n41)
{
    const float* in = blockIdx.z ? in1 : in0;
    __half* out     = blockIdx.z ? out1 : out0;
    int n4          = blockIdx.z ? n41 : n40;
    int i = blockIdx.x * 256 + threadIdx.x;
    if (i < n4) {
        float4 v = ((const float4*)in)[i];
        ((__half2*)out)[2 * i]     = __floats2half2_rn(v.x, v.y);
        ((__half2*)out)[2 * i + 1] = __floats2half2_rn(v.z, v.w);
    }
}

// W [K=DIM][N] rm -> Wt [N][K] rm (half). z selects which weight.
__global__ void __launch_bounds__(256)
transpose_half4(const float* __restrict__ W0, const float* __restrict__ W1,
                const float* __restrict__ W2, const float* __restrict__ W3)
{
    const float* W; size_t off; int N;
    switch (blockIdx.z) {
        case 0:  W = W0; off = WT_QKV_IN;  N = Q3;  break;
        case 1:  W = W1; off = WT_QKV_CTX; N = Q3;  break;
        case 2:  W = W2; off = WT_OUT_IN;  N = DIM; break;
        default: W = W3; off = WT_OUT_CTX; N = DIM; break;
    }
    if ((int)blockIdx.x * 32 >= N) return;
    __half* Wt = g_wt + off;
    __shared__ float t[32][33];
    int x  = blockIdx.x * 32 + threadIdx.x;   // n
    int y0 = blockIdx.y * 32 + threadIdx.y;   // k
    #pragma unroll
    for (int j = 0; j < 4; j++)
        t[threadIdx.y + j * 8][threadIdx.x] = W[(size_t)(y0 + j * 8) * N + x];
    __syncthreads();
    int x2 = blockIdx.y * 32 + threadIdx.x;   // k
    int y2 = blockIdx.x * 32 + threadIdx.y;   // n
    #pragma unroll
    for (int j = 0; j < 4; j++)
        Wt[(size_t)(y2 + j * 8) * DIM + x2] =
            __float2half_rn(t[threadIdx.x][threadIdx.y + j * 8]);
}

// ------------------------- F16 GEMM core -------------------------------------
// CTA tile 128x128, warp tile 64x32, k-chunk 64, 3-stage cp.async ring.
// 36.9 KB/stage -> 110.6 KB total -> 2 CTAs/SM (16 warps).
// Row stride 144B (128B data + 16 pad): ldsm conflict-free (36w % 32 = 4).
#define G_STAGE 36864
#define SM_GEMM (3 * G_STAGE)

__device__ __forceinline__ void gstore(__half* p, float x, float y) {
    *(__half2*)p = __floats2half2_rn(x, y);
}
__device__ __forceinline__ void gstore(float* p, float x, float y) {
    *(float2*)p = make_float2(x, y);
}

template <typename OutT>
__device__ __forceinline__ void gemm_core(
    const __half* __restrict__ Ap, const __half* __restrict__ Wp,
    const float* __restrict__ bp, OutT* __restrict__ Cp,
    int K, int N, char* smem)
{
    const unsigned sb = smem_u32(smem);
    const int tid  = threadIdx.x;
    const int lane = tid & 31;
    const int wid  = tid >> 5;
    const int wm   = (wid & 1) * 64;
    const int wn   = (wid >> 1) * 32;
    const int l4   = lane >> 2;
    const int lm   = lane & 3;
    const int NCH  = K / 64;

    const int lrow = tid >> 1;            // 0..127
    const int lcb  = (tid & 1) * 64;      // byte offset within 128B row
    auto issue = [&](int c, int st) {
        unsigned as = sb + st * G_STAGE;
        unsigned bs = as + 18432;
        const __half* ag = Ap + (size_t)lrow * K + c * 64 + lcb / 2;
        const __half* bg = Wp + (size_t)lrow * K + c * 64 + lcb / 2;
        #pragma unroll
        for (int j = 0; j < 4; j++) {
            cp16(as + lrow * 144 + lcb + j * 16, ag + j * 8);
            cp16(bs + lrow * 144 + lcb + j * 16, bg + j * 8);
        }
    };

    float acc[4][4][4];
    #pragma unroll
    for (int mi = 0; mi < 4; mi++)
        #pragma unroll
        for (int ni = 0; ni < 4; ni++)
            #pragma unroll
            for (int c = 0; c < 4; c++) acc[mi][ni][c] = 0.f;

    issue(0, 0); CP_COMMIT();
    issue(1, 1); CP_COMMIT();

    const unsigned a_off = (wm + (lane & 15)) * 144 + (lane >> 4) * 16;
    const unsigned b_off = 18432 + (wn + (lane & 15)) * 144 + (lane >> 4) * 16;

    for (int i = 0; i < NCH; i++) {
        CP_WAIT1();                       // chunk i resident
        __syncthreads();                  // slot (i+2)%3 readers done
        if (i + 2 < NCH) issue(i + 2, (i + 2) % 3);
        CP_COMMIT();

        unsigned st = sb + (i % 3) * G_STAGE;
        #pragma unroll
        for (int kp = 0; kp < 4; kp++) {
            unsigned af[4][4];
            #pragma unroll
            for (int mi = 0; mi < 4; mi++)
                ldsm4(af[mi], st + a_off + mi * 16 * 144 + kp * 32);
            #pragma unroll
            for (int nb = 0; nb < 2; nb++) {
                unsigned bf[4];
                ldsm4(bf, st + b_off + nb * 16 * 144 + kp * 32);
                #pragma unroll
                for (int mi = 0; mi < 4; mi++) {
                    mma16(acc[mi][2 * nb],     af[mi], bf[0], bf[2]);
                    mma16(acc[mi][2 * nb + 1], af[mi], bf[1], bf[3]);
                }
            }
        }
    }

    #pragma unroll
    for (int mi = 0; mi < 4; mi++) {
        #pragma unroll
        for (int ni = 0; ni < 4; ni++) {
            int r0 = wm + 16 * mi + l4;
            int c0 = wn + 8 * ni + 2 * lm;
            float bx = bp[c0], by = bp[c0 + 1];
            gstore(Cp + (size_t)r0 * N + c0,
                   acc[mi][ni][0] + bx, acc[mi][ni][1] + by);
            gstore(Cp + (size_t)(r0 + 8) * N + c0,
                   acc[mi][ni][2] + bx, acc[mi][ni][3] + by);
        }
    }
}

// merged QKV projections: y<32 -> input rows, y>=32 -> ctx rows
__global__ void __launch_bounds__(256, 2)
qkv_gemm(const float* __restrict__ b_in, const float* __restrict__ b_ctx)
{
    extern __shared__ char smem[];
    int y = blockIdx.y;
    const __half* A; const __half* W; const float* bias; __half* C;
    if (y < 32) {
        A = g_in_r + (size_t)y * 128 * DIM;
        W = g_wt + WT_QKV_IN;  bias = b_in;
        C = g_qkv_in + (size_t)y * 128 * Q3;
    } else {
        int y2 = y - 32;
        A = g_ctx_r + (size_t)y2 * 128 * DIM;
        W = g_wt + WT_QKV_CTX; bias = b_ctx;
        C = g_qkv_ctx + (size_t)y2 * 128 * Q3;
    }
    gemm_core<__half>(A, W + (size_t)blockIdx.x * 128 * DIM,
                      bias + blockIdx.x * 128, C + blockIdx.x * 128,
                      DIM, Q3, smem);
}

// merged output projections: y<32 -> input part (b = y>>4), else ctx part
__global__ void __launch_bounds__(256, 2)
out_gemm(const float* __restrict__ b_in, const float* __restrict__ b_ctx,
         float* __restrict__ out)
{
    extern __shared__ char smem[];
    int y = blockIdx.y;
    const __half* A; const __half* W; const float* bias; float* C;
    if (y < 32) {
        int b = y >> 4, yy = y & 15;
        A = g_o + ((size_t)b * NT + S_CTX + yy * 128) * DIM;
        W = g_wt + WT_OUT_IN;  bias = b_in;
        C = out + ((size_t)b * S_IN + yy * 128) * DIM;
    } else {
        int z = y - 32, b = z >> 1, yy = z & 1;
        A = g_o + ((size_t)b * NT + yy * 128) * DIM;
        W = g_wt + WT_OUT_CTX; bias = b_ctx;
        C = out + (size_t)BB * S_IN * DIM + ((size_t)b * S_CTX + yy * 128) * DIM;
    }
    gemm_core<float>(A, W + (size_t)blockIdx.x * 128 * DIM,
                     bias + blockIdx.x * 128, C + blockIdx.x * 128,
                     DIM, DIM, smem);
}

// ----------------- RMSNorm + RoPE + scatter (half -> half) -------------------
__global__ void __launch_bounds__(256)
normrope_kernel(const float* __restrict__ qs_in, const float* __restrict__ ks_in,
                const float* __restrict__ qs_ctx, const float* __restrict__ ks_ctx)
{
    const int pos = blockIdx.x;
    const int b   = blockIdx.y;
    const int t   = threadIdx.x;

    __shared__ float buf[DIM];
    __shared__ float red[8];
    __shared__ float cosv[64], sinv[64];

    const __half* src; const float* qs; const float* ks;
    if (pos < S_CTX) {
        src = g_qkv_ctx + ((size_t)b * S_CTX + pos) * Q3;
        qs = qs_ctx; ks = ks_ctx;
    } else {
        src = g_qkv_in + ((size_t)b * S_IN + (pos - S_CTX)) * Q3;
        qs = qs_in; ks = ks_in;
    }

    if (t < 64) {
        float2 cs = g_rope[(size_t)pos * 64 + t];
        cosv[t] = cs.x;
        sinv[t] = cs.y;
    }

    const float qscale = 0.088388347648318447f;   // 128^-0.5

    #pragma unroll
    for (int which = 0; which < 2; which++) {
        const __half* x  = src + which * DIM;
        const float*  sc = which ? ks : qs;
        float v[6];
        float local = 0.f;
        #pragma unroll
        for (int i = 0; i < 6; i++) {
            v[i] = __half2float(x[t + i * 256]);
            local = fmaf(v[i], v[i], local);
        }
        #pragma unroll
        for (int off = 16; off; off >>= 1)
            local += __shfl_xor_sync(0xffffffffu, local, off);
        if ((t & 31) == 0) red[t >> 5] = local;
        __syncthreads();
        float tot = red[0] + red[1] + red[2] + red[3]
                  + red[4] + red[5] + red[6] + red[7];
        float r = rsqrtf(tot * (1.0f / DIM) + 1e-6f);
        #pragma unroll
        for (int i = 0; i < 6; i++)
            buf[t + i * 256] = v[i] * r * sc[t + i * 256];
        __syncthreads();

        __half* dst = which ? g_k : g_q;
        float post = which ? 1.0f : qscale;
        #pragma unroll
        for (int i = 0; i < 6; i++) {
            int e = t + i * 256;
            int hh = e >> 7, d = e & 127, j = d & 63;
            float c = cosv[j], sn = sinv[j];
            float y = (d < 64) ? (buf[e] * c - buf[e + 64] * sn)
                               : (buf[e] * c + buf[e - 64] * sn);
            dst[(((size_t)b * NH + hh) * NT + pos) * HD + d] =
                __float2half_rn(y * post);
        }
        __syncthreads();
    }

    // V: copy to [b][h][n][d] (coalesced 256B chunks per head)
    #pragma unroll
    for (int i = 0; i < 6; i++) {
        int e = t + i * 256;
        int hh = e >> 7, d = e & 127;
        g_v[(((size_t)b * NH + hh) * NT + pos) * HD + d] = src[2 * DIM + e];
    }
}

// ------------------------- F16 flash attention -------------------------------
// 96-query tile, 192 thr / 6 warps, 2 CTAs/SM (barriers/softmax of the two
// CTAs overlap). K+V double-buffered (2-slot ring, one commit group/ktile).
// V row-major; PV B-fragments via ldmatrix.trans.
// Smem: Qs 96x272 | K 2x(64x272) | V 2x(64x272) | Ps 96x144  = 107 KB
#define ATT_QS   0
#define ATT_K    26112
#define ATT_V    60928
#define ATT_PS   95744
#define SM_ATTN  109568

__global__ void __launch_bounds__(192, 2)
attn_kernel(void)
{
    extern __shared__ char smem[];
    const unsigned sb = smem_u32(smem);

    const int qt = blockIdx.x, h = blockIdx.y, b = blockIdx.z;
    const size_t base = (((size_t)b * NH + h) * NT) * HD;
    const __half* Qg = g_q + base + (size_t)qt * 96 * HD;
    const __half* Kg = g_k + base;
    const __half* Vg = g_v + base;

    const int tid  = threadIdx.x;
    const int lane = tid & 31;
    const int wid  = tid >> 5;        // 0..5
    const int l4   = lane >> 2;
    const int lm   = lane & 3;
    const int q0   = wid * 16;

    auto load_KV = [&](int kt, int slot) {
        unsigned kdst = sb + ATT_K + slot * 17408;
        unsigned vdst = sb + ATT_V + slot * 17408;
        const __half* ks = Kg + (size_t)kt * 64 * HD;
        const __half* vs = Vg + (size_t)kt * 64 * HD;
        for (int lin = tid; lin < 1024; lin += 192) {
            int row = lin >> 4, ch = lin & 15;
            cp16(kdst + row * 272 + ch * 16, ks + row * 128 + ch * 8);
            cp16(vdst + row * 272 + ch * 16, vs + row * 128 + ch * 8);
        }
    };

    // prologue: Q (group 0), KV0 (group 1), KV1 (group 2)
    for (int lin = tid; lin < 1536; lin += 192) {
        int row = lin >> 4, ch = lin & 15;
        cp16(sb + ATT_QS + row * 272 + ch * 16, Qg + row * 128 + ch * 8);
    }
    CP_COMMIT();
    load_KV(0, 0); CP_COMMIT();
    load_KV(1, 1); CP_COMMIT();

    float O[16][4];
    #pragma unroll
    for (int ni = 0; ni < 16; ni++)
        #pragma unroll
        for (int c = 0; c < 4; c++) O[ni][c] = 0.f;
    float m0 = -1e30f, m1 = -1e30f, l0 = 0.f, l1 = 0.f;

    const unsigned qa = sb + ATT_QS + (q0 + (lane & 15)) * 272 + (lane >> 4) * 16;
    const unsigned kb = (lane & 15) * 272 + (lane >> 4) * 16;
    const unsigned pa = sb + ATT_PS + (q0 + (lane & 15)) * 144 + (lane >> 4) * 16;
    const unsigned vtb = ((lane & 7) + ((lane >> 4) << 3)) * 272
                       + ((lane >> 3) & 1) * 16;

    for (int kt = 0; kt < NKT; kt++) {
        const int slot = kt & 1;
        CP_WAIT1();            // KV(kt) ready (KV(kt+1) may pend)
        __syncthreads();

        // ---- S = Q @ K^T ----
        const unsigned kbase = sb + ATT_K + slot * 17408 + kb;
        float s[8][4];
        #pragma unroll
        for (int ni = 0; ni < 8; ni++)
            #pragma unroll
            for (int c = 0; c < 4; c++) s[ni][c] = 0.f;

        #pragma unroll
        for (int kp = 0; kp < 8; kp++) {
            unsigned a[4];
            ldsm4(a, qa + kp * 32);
            #pragma unroll
            for (int nb = 0; nb < 4; nb++) {
                unsigned bf[4];
                ldsm4(bf, kbase + nb * 16 * 272 + kp * 32);
                mma16(s[2 * nb],     a, bf[0], bf[2]);
                mma16(s[2 * nb + 1], a, bf[1], bf[3]);
            }
        }

        // ---- online softmax (rows are warp-private) ----
        float mx0 = -1e30f, mx1 = -1e30f;
        #pragma unroll
        for (int ni = 0; ni < 8; ni++) {
            mx0 = fmaxf(mx0, fmaxf(s[ni][0], s[ni][1]));
            mx1 = fmaxf(mx1, fmaxf(s[ni][2], s[ni][3]));
        }
        mx0 = fmaxf(mx0, __shfl_xor_sync(0xffffffffu, mx0, 1));
        mx0 = fmaxf(mx0, __shfl_xor_sync(0xffffffffu, mx0, 2));
        mx1 = fmaxf(mx1, __shfl_xor_sync(0xffffffffu, mx1, 1));
        mx1 = fmaxf(mx1, __shfl_xor_sync(0xffffffffu, mx1, 2));

        float mn0 = fmaxf(m0, mx0), mn1 = fmaxf(m1, mx1);
        float al0 = fexp(m0 - mn0), al1 = fexp(m1 - mn1);
        float ls0 = 0.f, ls1 = 0.f;
        #pragma unroll
        for (int ni = 0; ni < 8; ni++) {
            float p0 = fexp(s[ni][0] - mn0);
            float p1 = fexp(s[ni][1] - mn0);
            float p2 = fexp(s[ni][2] - mn1);
            float p3 = fexp(s[ni][3] - mn1);
            ls0 += p0 + p1; ls1 += p2 + p3;
            int cb = (ni * 8 + lm * 2) * 2;
            *(__half2*)(smem + ATT_PS + (q0 + l4) * 144 + cb) =
                __floats2half2_rn(p0, p1);
            *(__half2*)(smem + ATT_PS + (q0 + l4 + 8) * 144 + cb) =
                __floats2half2_rn(p2, p3);
        }
        ls0 += __shfl_xor_sync(0xffffffffu, ls0, 1);
        ls0 += __shfl_xor_sync(0xffffffffu, ls0, 2);
        ls1 += __shfl_xor_sync(0xffffffffu, ls1, 1);
        ls1 += __shfl_xor_sync(0xffffffffu, ls1, 2);
        l0 = l0 * al0 + ls0;  m0 = mn0;
        l1 = l1 * al1 + ls1;  m1 = mn1;
        #pragma unroll
        for (int ni = 0; ni < 16; ni++) {
            O[ni][0] *= al0; O[ni][1] *= al0;
            O[ni][2] *= al1; O[ni][3] *= al1;
        }
        __syncwarp();          // P stores visible to this warp's ldsm

        // ---- O += P @ V (V row-major, trans ldmatrix) ----
        const unsigned vbase = sb + ATT_V + slot * 17408 + vtb;
        #pragma unroll
        for (int kp = 0; kp < 4; kp++) {
            unsigned a[4];
            ldsm4(a, pa + kp * 32);
            #pragma unroll
            for (int g = 0; g < 8; g++) {
                unsigned bf[4];
                ldsm4t(bf, vbase + kp * 16 * 272 + g * 32);
                mma16(O[2 * g],     a, bf[0], bf[2]);
                mma16(O[2 * g + 1], a, bf[1], bf[3]);
            }
        }

        __syncthreads();       // all warps done reading slot
        if (kt + 2 < NKT) load_KV(kt + 2, slot);
        CP_COMMIT();
    }

    // epilogue
    float inv0 = 1.0f / l0, inv1 = 1.0f / l1;
    size_t r0 = (size_t)qt * 96 + q0 + l4;
    __half* op0 = g_o + ((size_t)b * NT + r0) * DIM + h * HD;
    __half* op1 = g_o + ((size_t)b * NT + r0 + 8) * DIM + h * HD;
    #pragma unroll
    for (int ni = 0; ni < 16; ni++) {
        int cc = ni * 8 + lm * 2;
        *(__half2*)(op0 + cc) = __floats2half2_rn(O[ni][0] * inv0,
                                                  O[ni][1] * inv0);
        *(__half2*)(op1 + cc) = __floats2half2_rn(O[ni][2] * inv1,
                                                  O[ni][3] * inv1);
    }
}

// ------------------------- launch --------------------------------------------
extern "C" void kernel_launch(void* const* d_in, const int* in_sizes, int n_in,
                              void* d_out, int out_size)
{
    (void)in_sizes; (void)n_in; (void)out_size;

    const float* input     = (const float*)d_in[0];
    const float* context   = (const float*)d_in[1];
    const float* W_qkv_in  = (const float*)d_in[2];
    const float* b_qkv_in  = (const float*)d_in[3];
    const float* W_qkv_ctx = (const float*)d_in[4];
    const float* b_qkv_ctx = (const float*)d_in[5];
    const float* qs_in     = (const float*)d_in[6];
    const float* ks_in     = (const float*)d_in[7];
    const float* qs_ctx    = (const float*)d_in[8];
    const float* ks_ctx    = (const float*)d_in[9];
    const float* W_out_in  = (const float*)d_in[10];
    const float* b_out_in  = (const float*)d_in[11];
    const float* W_out_ctx = (const float*)d_in[12];
    const float* b_out_ctx = (const float*)d_in[13];
    float* out = (float*)d_out;

    __half *in_r, *ctx_r;
    cudaGetSymbolAddress((void**)&in_r,  g_in_r);
    cudaGetSymbolAddress((void**)&ctx_r, g_ctx_r);

    cudaFuncSetAttribute(qkv_gemm,
                         cudaFuncAttributeMaxDynamicSharedMemorySize, SM_GEMM);
    cudaFuncSetAttribute(out_gemm,
                         cudaFuncAttributeMaxDynamicSharedMemorySize, SM_GEMM);
    cudaFuncSetAttribute(attn_kernel,
                         cudaFuncAttributeMaxDynamicSharedMemorySize, SM_ATTN);

    // 0) prep: conversions, weight transpose, rope table
    {
        int n40 = BB * S_IN  * DIM / 4;
        int n41 = BB * S_CTX * DIM / 4;
        half_copy2<<<dim3((n40 + 255) / 256, 1, 2), 256>>>(
            input, in_r, n40, context, ctx_r, n41);
    }
    transpose_half4<<<dim3(Q3 / 32, DIM / 32, 4), dim3(32, 8)>>>(
        W_qkv_in, W_qkv_ctx, W_out_in, W_out_ctx);
    rope_table<<<NT, 64>>>();

    // 1) QKV projections (merged, 128x128 CTA tiles)
    qkv_gemm<<<dim3(Q3 / 128, 36), 256, SM_GEMM>>>(b_qkv_in, b_qkv_ctx);

    // 2) RMSNorm + RoPE + scatter
    normrope_kernel<<<dim3(NT, BB), 256>>>(qs_in, ks_in, qs_ctx, ks_ctx);

    // 3) Attention (96-query tiles, 2 CTAs/SM)
    attn_kernel<<<dim3(NT / 96, NH, BB), 192, SM_ATTN>>>();

    // 4) Output projections (merged)
    out_gemm<<<dim3(DIM / 128, 36), 256, SM_GEMM>>>(b_out_in, b_out_ctx, out);
}

// round 12
// speedup vs baseline: 1.0963x; 1.0963x over previous
#include <cuda_runtime.h>
#include <cuda_fp16.h>
#include <math.h>
#include <stdint.h>

#define NH    12
#define HD    128
#define DIM   1536
#define BB    2
#define S_IN  2048
#define S_CTX 256
#define NT    (S_IN + S_CTX)   // 2304
#define Q3    (3 * DIM)        // 4608
#define NKT   (NT / 64)        // 36

// ------------------------- scratch (no cudaMalloc allowed) -------------------
static __device__ __half g_qkv_in [(size_t)BB * S_IN  * Q3];
static __device__ __half g_qkv_ctx[(size_t)BB * S_CTX * Q3];
static __device__ __half g_q[(size_t)BB * NH * NT * HD];   // scaled, [b][h][n][d]
static __device__ __half g_k[(size_t)BB * NH * NT * HD];   // [b][h][n][d]
static __device__ __half g_v[(size_t)BB * NH * NT * HD];   // [b][h][n][d]
static __device__ __half g_o[(size_t)BB * NT * DIM];
static __device__ __half g_wt[18874368];                   // transposed weights
static __device__ __half g_in_r [(size_t)BB * S_IN  * DIM];
static __device__ __half g_ctx_r[(size_t)BB * S_CTX * DIM];
static __device__ float2 g_rope[(size_t)NT * 64];          // (cos, sin)

#define WT_QKV_IN  0
#define WT_QKV_CTX 7077888
#define WT_OUT_IN  14155776
#define WT_OUT_CTX 16515072

// ------------------------- helpers -------------------------------------------
__device__ __forceinline__ unsigned smem_u32(const void* p) {
    unsigned a;
    asm("{ .reg .u64 t; cvta.to.shared.u64 t, %1; cvt.u32.u64 %0, t; }"
        : "=r"(a) : "l"(p));
    return a;
}

__device__ __forceinline__ void cp16(unsigned s, const void* g) {
    unsigned long long ga;
    asm("cvta.to.global.u64 %0, %1;" : "=l"(ga) : "l"(g));
    asm volatile("cp.async.cg.shared.global [%0], [%1], 16;"
                 :: "r"(s), "l"(ga));
}
#define CP_COMMIT() asm volatile("cp.async.commit_group;" ::: "memory")
#define CP_WAIT0()  asm volatile("cp.async.wait_group 0;" ::: "memory")
#define CP_WAIT1()  asm volatile("cp.async.wait_group 1;" ::: "memory")
#define CP_WAIT2()  asm volatile("cp.async.wait_group 2;" ::: "memory")

__device__ __forceinline__ void ldsm4(unsigned* r, unsigned addr) {
    asm volatile("ldmatrix.sync.aligned.m8n8.x4.shared.b16 {%0,%1,%2,%3}, [%4];"
        : "=r"(r[0]), "=r"(r[1]), "=r"(r[2]), "=r"(r[3]) : "r"(addr));
}

__device__ __forceinline__ void ldsm4t(unsigned* r, unsigned addr) {
    asm volatile("ldmatrix.sync.aligned.m8n8.x4.trans.shared.b16 {%0,%1,%2,%3}, [%4];"
        : "=r"(r[0]), "=r"(r[1]), "=r"(r[2]), "=r"(r[3]) : "r"(addr));
}

__device__ __forceinline__ void mma16(float* c, const unsigned* a,
                                      unsigned b0, unsigned b1) {
    asm volatile(
        "mma.sync.aligned.m16n8k16.row.col.f32.f16.f16.f32 "
        "{%0,%1,%2,%3}, {%4,%5,%6,%7}, {%8,%9}, {%0,%1,%2,%3};"
        : "+f"(c[0]), "+f"(c[1]), "+f"(c[2]), "+f"(c[3])
        : "r"(a[0]), "r"(a[1]), "r"(a[2]), "r"(a[3]), "r"(b0), "r"(b1));
}

__device__ __forceinline__ float fexp(float x) {
    float r;
    asm("ex2.approx.ftz.f32 %0, %1;" : "=f"(r) : "f"(x * 1.4426950408889634f));
    return r;
}

// ------------------------- one-shot RoPE table -------------------------------
__global__ void __launch_bounds__(64)
rope_table(void)
{
    int pos = blockIdx.x;
    int t   = threadIdx.x;
    double ang = (double)pos * pow(10000.0, -(double)t / 64.0);
    g_rope[(size_t)pos * 64 + t] = make_float2((float)cos(ang), (float)sin(ang));
}

// ------------------------- merged prep kernels -------------------------------
__global__ void __launch_bounds__(256)
half_copy2(const float* __restrict__ in0, __half* __restrict__ out0, int n40,
           const float* __restrict__ in1, __half* __restrict__ out1, int n41)
{
    const float* in = blockIdx.z ? in1 : in0;
    __half* out     = blockIdx.z ? out1 : out0;
    int n4          = blockIdx.z ? n41 : n40;
    int i = blockIdx.x * 256 + threadIdx.x;
    if (i < n4) {
        float4 v = ((const float4*)in)[i];
        ((__half2*)out)[2 * i]     = __floats2half2_rn(v.x, v.y);
        ((__half2*)out)[2 * i + 1] = __floats2half2_rn(v.z, v.w);
    }
}

// W [K=DIM][N] rm -> Wt [N][K] rm (half). z selects which weight.
__global__ void __launch_bounds__(256)
transpose_half4(const float* __restrict__ W0, const float* __restrict__ W1,
                const float* __restrict__ W2, const float* __restrict__ W3)
{
    const float* W; size_t off; int N;
    switch (blockIdx.z) {
        case 0:  W = W0; off = WT_QKV_IN;  N = Q3;  break;
        case 1:  W = W1; off = WT_QKV_CTX; N = Q3;  break;
        case 2:  W = W2; off = WT_OUT_IN;  N = DIM; break;
        default: W = W3; off = WT_OUT_CTX; N = DIM; break;
    }
    if ((int)blockIdx.x * 32 >= N) return;
    __half* Wt = g_wt + off;
    __shared__ float t[32][33];
    int x  = blockIdx.x * 32 + threadIdx.x;   // n
    int y0 = blockIdx.y * 32 + threadIdx.y;   // k
    #pragma unroll
    for (int j = 0; j < 4; j++)
        t[threadIdx.y + j * 8][threadIdx.x] = W[(size_t)(y0 + j * 8) * N + x];
    __syncthreads();
    int x2 = blockIdx.y * 32 + threadIdx.x;   // k
    int y2 = blockIdx.x * 32 + threadIdx.y;   // n
    #pragma unroll
    for (int j = 0; j < 4; j++)
        Wt[(size_t)(y2 + j * 8) * DIM + x2] =
            __float2half_rn(t[threadIdx.x][threadIdx.y + j * 8]);
}

// ------------------------- F16 GEMM core (R10 config) ------------------------
// CTA tile 128x128, warp tile 64x32, k-chunk 32, 4-stage cp.async ring.
// 20.5 KB/stage -> 82 KB total -> 2 CTAs/SM (16 warps).
#define G_STAGE 20480
#define SM_GEMM (4 * G_STAGE)

__device__ __forceinline__ void gstore(__half* p, float x, float y) {
    *(__half2*)p = __floats2half2_rn(x, y);
}
__device__ __forceinline__ void gstore(float* p, float x, float y) {
    *(float2*)p = make_float2(x, y);
}

template <typename OutT>
__device__ __forceinline__ void gemm_core(
    const __half* __restrict__ Ap, const __half* __restrict__ Wp,
    const float* __restrict__ bp, OutT* __restrict__ Cp,
    int K, int N, char* smem)
{
    const unsigned sb = smem_u32(smem);
    const int tid  = threadIdx.x;
    const int lane = tid & 31;
    const int wid  = tid >> 5;
    const int wm   = (wid & 1) * 64;
    const int wn   = (wid >> 1) * 32;
    const int l4   = lane >> 2;
    const int lm   = lane & 3;
    const int NCH  = K / 32;

    const int lrow = tid >> 1;            // 0..127
    const int lcb  = (tid & 1) * 32;      // byte offset within 64B row
    auto issue = [&](int c, int st) {
        unsigned as = sb + st * G_STAGE;
        unsigned bs = as + 10240;
        const __half* ag = Ap + (size_t)lrow * K + c * 32 + lcb / 2;
        cp16(as + lrow * 80 + lcb, ag);
        cp16(as + lrow * 80 + lcb + 16, ag + 8);
        const __half* bg = Wp + (size_t)lrow * K + c * 32 + lcb / 2;
        cp16(bs + lrow * 80 + lcb, bg);
        cp16(bs + lrow * 80 + lcb + 16, bg + 8);
    };

    float acc[4][4][4];
    #pragma unroll
    for (int mi = 0; mi < 4; mi++)
        #pragma unroll
        for (int ni = 0; ni < 4; ni++)
            #pragma unroll
            for (int c = 0; c < 4; c++) acc[mi][ni][c] = 0.f;

    issue(0, 0); CP_COMMIT();
    issue(1, 1); CP_COMMIT();
    issue(2, 2); CP_COMMIT();

    const unsigned a_off = (wm + (lane & 15)) * 80 + (lane >> 4) * 16;
    const unsigned b_off = 10240 + (wn + (lane & 15)) * 80 + (lane >> 4) * 16;

    for (int i = 0; i < NCH; i++) {
        CP_WAIT2();
        __syncthreads();
        if (i + 3 < NCH) issue(i + 3, (i + 3) & 3);
        CP_COMMIT();

        unsigned st = sb + (i & 3) * G_STAGE;
        #pragma unroll
        for (int kp = 0; kp < 2; kp++) {
            unsigned af[4][4];
            #pragma unroll
            for (int mi = 0; mi < 4; mi++)
                ldsm4(af[mi], st + a_off + mi * 16 * 80 + kp * 32);
            #pragma unroll
            for (int nb = 0; nb < 2; nb++) {
                unsigned bf[4];
                ldsm4(bf, st + b_off + nb * 16 * 80 + kp * 32);
                #pragma unroll
                for (int mi = 0; mi < 4; mi++) {
                    mma16(acc[mi][2 * nb],     af[mi], bf[0], bf[2]);
                    mma16(acc[mi][2 * nb + 1], af[mi], bf[1], bf[3]);
                }
            }
        }
    }

    #pragma unroll
    for (int mi = 0; mi < 4; mi++) {
        #pragma unroll
        for (int ni = 0; ni < 4; ni++) {
            int r0 = wm + 16 * mi + l4;
            int c0 = wn + 8 * ni + 2 * lm;
            float bx = bp[c0], by = bp[c0 + 1];
            gstore(Cp + (size_t)r0 * N + c0,
                   acc[mi][ni][0] + bx, acc[mi][ni][1] + by);
            gstore(Cp + (size_t)(r0 + 8) * N + c0,
                   acc[mi][ni][2] + bx, acc[mi][ni][3] + by);
        }
    }
}

// merged QKV projections: y<32 -> input rows, y>=32 -> ctx rows
__global__ void __launch_bounds__(256, 2)
qkv_gemm(const float* __restrict__ b_in, const float* __restrict__ b_ctx)
{
    extern __shared__ char smem[];
    int y = blockIdx.y;
    const __half* A; const __half* W; const float* bias; __half* C;
    if (y < 32) {
        A = g_in_r + (size_t)y * 128 * DIM;
        W = g_wt + WT_QKV_IN;  bias = b_in;
        C = g_qkv_in + (size_t)y * 128 * Q3;
    } else {
        int y2 = y - 32;
        A = g_ctx_r + (size_t)y2 * 128 * DIM;
        W = g_wt + WT_QKV_CTX; bias = b_ctx;
        C = g_qkv_ctx + (size_t)y2 * 128 * Q3;
    }
    gemm_core<__half>(A, W + (size_t)blockIdx.x * 128 * DIM,
                      bias + blockIdx.x * 128, C + blockIdx.x * 128,
                      DIM, Q3, smem);
}

// merged output projections: y<32 -> input part (b = y>>4), else ctx part
__global__ void __launch_bounds__(256, 2)
out_gemm(const float* __restrict__ b_in, const float* __restrict__ b_ctx,
         float* __restrict__ out)
{
    extern __shared__ char smem[];
    int y = blockIdx.y;
    const __half* A; const __half* W; const float* bias; float* C;
    if (y < 32) {
        int b = y >> 4, yy = y & 15;
        A = g_o + ((size_t)b * NT + S_CTX + yy * 128) * DIM;
        W = g_wt + WT_OUT_IN;  bias = b_in;
        C = out + ((size_t)b * S_IN + yy * 128) * DIM;
    } else {
        int z = y - 32, b = z >> 1, yy = z & 1;
        A = g_o + ((size_t)b * NT + yy * 128) * DIM;
        W = g_wt + WT_OUT_CTX; bias = b_ctx;
        C = out + (size_t)BB * S_IN * DIM + ((size_t)b * S_CTX + yy * 128) * DIM;
    }
    gemm_core<float>(A, W + (size_t)blockIdx.x * 128 * DIM,
                     bias + blockIdx.x * 128, C + blockIdx.x * 128,
                     DIM, DIM, smem);
}

// ----------------- RMSNorm + RoPE + scatter (half -> half) -------------------
__global__ void __launch_bounds__(256)
normrope_kernel(const float* __restrict__ qs_in, const float* __restrict__ ks_in,
                const float* __restrict__ qs_ctx, const float* __restrict__ ks_ctx)
{
    const int pos = blockIdx.x;
    const int b   = blockIdx.y;
    const int t   = threadIdx.x;

    __shared__ float buf[DIM];
    __shared__ float red[8];
    __shared__ float cosv[64], sinv[64];

    const __half* src; const float* qs; const float* ks;
    if (pos < S_CTX) {
        src = g_qkv_ctx + ((size_t)b * S_CTX + pos) * Q3;
        qs = qs_ctx; ks = ks_ctx;
    } else {
        src = g_qkv_in + ((size_t)b * S_IN + (pos - S_CTX)) * Q3;
        qs = qs_in; ks = ks_in;
    }

    if (t < 64) {
        float2 cs = g_rope[(size_t)pos * 64 + t];
        cosv[t] = cs.x;
        sinv[t] = cs.y;
    }

    const float qscale = 0.088388347648318447f;   // 128^-0.5

    #pragma unroll
    for (int which = 0; which < 2; which++) {
        const __half* x  = src + which * DIM;
        const float*  sc = which ? ks : qs;
        float v[6];
        float local = 0.f;
        #pragma unroll
        for (int i = 0; i < 6; i++) {
            v[i] = __half2float(x[t + i * 256]);
            local = fmaf(v[i], v[i], local);
        }
        #pragma unroll
        for (int off = 16; off; off >>= 1)
            local += __shfl_xor_sync(0xffffffffu, local, off);
        if ((t & 31) == 0) red[t >> 5] = local;
        __syncthreads();
        float tot = red[0] + red[1] + red[2] + red[3]
                  + red[4] + red[5] + red[6] + red[7];
        float r = rsqrtf(tot * (1.0f / DIM) + 1e-6f);
        #pragma unroll
        for (int i = 0; i < 6; i++)
            buf[t + i * 256] = v[i] * r * sc[t + i * 256];
        __syncthreads();

        __half* dst = which ? g_k : g_q;
        float post = which ? 1.0f : qscale;
        #pragma unroll
        for (int i = 0; i < 6; i++) {
            int e = t + i * 256;
            int hh = e >> 7, d = e & 127, j = d & 63;
            float c = cosv[j], sn = sinv[j];
            float y = (d < 64) ? (buf[e] * c - buf[e + 64] * sn)
                               : (buf[e] * c + buf[e - 64] * sn);
            dst[(((size_t)b * NH + hh) * NT + pos) * HD + d] =
                __float2half_rn(y * post);
        }
        __syncthreads();
    }

    // V: copy to [b][h][n][d] (coalesced 256B chunks per head)
    #pragma unroll
    for (int i = 0; i < 6; i++) {
        int e = t + i * 256;
        int hh = e >> 7, d = e & 127;
        g_v[(((size_t)b * NH + hh) * NT + pos) * HD + d] = src[2 * DIM + e];
    }
}

// ------------------------- F16 flash attention -------------------------------
// 192-query tile, 192 thr / 6 warps, 32 q-rows per warp (two 16-row subtiles
// sharing every K/V B-fragment -> ldsm/mma drops 0.59 -> 0.34).
// K+V triple-buffered together, ONE __syncthreads + one wait per ktile.
// V row-major; PV B-fragments via ldmatrix.trans. P warp-private.
// Smem: Qs 192x272 | K 3x(64x272) | V 3x(64x272) | Ps 192x144 (same as R10)
#define ATT_QS   0
#define ATT_K    52224
#define ATT_V    104448
#define ATT_PS   156672
#define SM_ATTN  184320

__global__ void __launch_bounds__(192, 1)
attn_kernel(void)
{
    extern __shared__ char smem[];
    const unsigned sb = smem_u32(smem);

    const int qt = blockIdx.x, h = blockIdx.y, b = blockIdx.z;
    const size_t base = (((size_t)b * NH + h) * NT) * HD;
    const __half* Qg = g_q + base + (size_t)qt * 192 * HD;
    const __half* Kg = g_k + base;
    const __half* Vg = g_v + base;

    const int tid  = threadIdx.x;
    const int lane = tid & 31;
    const int wid  = tid >> 5;        // 0..5
    const int l4   = lane >> 2;
    const int lm   = lane & 3;
    const int q0   = wid * 32;        // warp owns rows q0..q0+31

    auto load_KV = [&](int kt, int slot) {
        unsigned kdst = sb + ATT_K + slot * 17408;
        unsigned vdst = sb + ATT_V + slot * 17408;
        const __half* ks = Kg + (size_t)kt * 64 * HD;
        const __half* vs = Vg + (size_t)kt * 64 * HD;
        for (int lin = tid; lin < 1024; lin += 192) {
            int row = lin >> 4, ch = lin & 15;
            cp16(kdst + row * 272 + ch * 16, ks + row * 128 + ch * 8);
            cp16(vdst + row * 272 + ch * 16, vs + row * 128 + ch * 8);
        }
    };

    // prologue: Q (group 0), KV0 (group 1), KV1 (group 2)
    for (int lin = tid; lin < 3072; lin += 192) {
        int row = lin >> 4, ch = lin & 15;
        cp16(sb + ATT_QS + row * 272 + ch * 16, Qg + row * 128 + ch * 8);
    }
    CP_COMMIT();
    load_KV(0, 0); CP_COMMIT();
    load_KV(1, 1); CP_COMMIT();

    float O0[16][4], O1[16][4];
    #pragma unroll
    for (int ni = 0; ni < 16; ni++)
        #pragma unroll
        for (int c = 0; c < 4; c++) { O0[ni][c] = 0.f; O1[ni][c] = 0.f; }
    float m00 = -1e30f, m01 = -1e30f, m10 = -1e30f, m11 = -1e30f;
    float l00 = 0.f, l01 = 0.f, l10 = 0.f, l11 = 0.f;

    const unsigned qa = sb + ATT_QS + (q0 + (lane & 15)) * 272 + (lane >> 4) * 16;
    const unsigned kb = (lane & 15) * 272 + (lane >> 4) * 16;
    const unsigned pa = sb + ATT_PS + (q0 + (lane & 15)) * 144 + (lane >> 4) * 16;
    // trans-V lane base
    const unsigned vtb = ((lane & 7) + ((lane >> 4) << 3)) * 272
                       + ((lane >> 3) & 1) * 16;

    for (int kt = 0; kt < NKT; kt++) {
        const int slot = kt % 3;
        CP_WAIT1();            // Q + KV(kt) resident
        __syncthreads();       // slot (kt+2)%3 readers (iter kt-1) done
        if (kt + 2 < NKT) load_KV(kt + 2, (kt + 2) % 3);
        CP_COMMIT();

        // ---- S = Q @ K^T (both 16-row subtiles share every K fragment) ----
        const unsigned kbase = sb + ATT_K + slot * 17408 + kb;
        float s0[8][4], s1[8][4];
        #pragma unroll
        for (int ni = 0; ni < 8; ni++)
            #pragma unroll
            for (int c = 0; c < 4; c++) { s0[ni][c] = 0.f; s1[ni][c] = 0.f; }

        #pragma unroll
        for (int kp = 0; kp < 8; kp++) {
            unsigned a0[4], a1[4];
            ldsm4(a0, qa + kp * 32);
            ldsm4(a1, qa + 16 * 272 + kp * 32);
            #pragma unroll
            for (int nb = 0; nb < 4; nb++) {
                unsigned bf[4];
                ldsm4(bf, kbase + nb * 16 * 272 + kp * 32);
                mma16(s0[2 * nb],     a0, bf[0], bf[2]);
                mma16(s0[2 * nb + 1], a0, bf[1], bf[3]);
                mma16(s1[2 * nb],     a1, bf[0], bf[2]);
                mma16(s1[2 * nb + 1], a1, bf[1], bf[3]);
            }
        }

        // ---- online softmax, subtile 0 ----
        {
            float mx0 = -1e30f, mx1 = -1e30f;
            #pragma unroll
            for (int ni = 0; ni < 8; ni++) {
                mx0 = fmaxf(mx0, fmaxf(s0[ni][0], s0[ni][1]));
                mx1 = fmaxf(mx1, fmaxf(s0[ni][2], s0[ni][3]));
            }
            mx0 = fmaxf(mx0, __shfl_xor_sync(0xffffffffu, mx0, 1));
            mx0 = fmaxf(mx0, __shfl_xor_sync(0xffffffffu, mx0, 2));
            mx1 = fmaxf(mx1, __shfl_xor_sync(0xffffffffu, mx1, 1));
            mx1 = fmaxf(mx1, __shfl_xor_sync(0xffffffffu, mx1, 2));
            float mn0 = fmaxf(m00, mx0), mn1 = fmaxf(m01, mx1);
            float al0 = fexp(m00 - mn0), al1 = fexp(m01 - mn1);
            float ls0 = 0.f, ls1 = 0.f;
            #pragma unroll
            for (int ni = 0; ni < 8; ni++) {
                float p0 = fexp(s0[ni][0] - mn0);
                float p1 = fexp(s0[ni][1] - mn0);
                float p2 = fexp(s0[ni][2] - mn1);
                float p3 = fexp(s0[ni][3] - mn1);
                ls0 += p0 + p1; ls1 += p2 + p3;
                int cb = (ni * 8 + lm * 2) * 2;
                *(__half2*)(smem + ATT_PS + (q0 + l4) * 144 + cb) =
                    __floats2half2_rn(p0, p1);
                *(__half2*)(smem + ATT_PS + (q0 + l4 + 8) * 144 + cb) =
                    __floats2half2_rn(p2, p3);
            }
            ls0 += __shfl_xor_sync(0xffffffffu, ls0, 1);
            ls0 += __shfl_xor_sync(0xffffffffu, ls0, 2);
            ls1 += __shfl_xor_sync(0xffffffffu, ls1, 1);
            ls1 += __shfl_xor_sync(0xffffffffu, ls1, 2);
            l00 = l00 * al0 + ls0;  m00 = mn0;
            l01 = l01 * al1 + ls1;  m01 = mn1;
            #pragma unroll
            for (int ni = 0; ni < 16; ni++) {
                O0[ni][0] *= al0; O0[ni][1] *= al0;
                O0[ni][2] *= al1; O0[ni][3] *= al1;
            }
        }
        // ---- online softmax, subtile 1 ----
        {
            float mx0 = -1e30f, mx1 = -1e30f;
            #pragma unroll
            for (int ni = 0; ni < 8; ni++) {
                mx0 = fmaxf(mx0, fmaxf(s1[ni][0], s1[ni][1]));
                mx1 = fmaxf(mx1, fmaxf(s1[ni][2], s1[ni][3]));
            }
            mx0 = fmaxf(mx0, __shfl_xor_sync(0xffffffffu, mx0, 1));
            mx0 = fmaxf(mx0, __shfl_xor_sync(0xffffffffu, mx0, 2));
            mx1 = fmaxf(mx1, __shfl_xor_sync(0xffffffffu, mx1, 1));
            mx1 = fmaxf(mx1, __shfl_xor_sync(0xffffffffu, mx1, 2));
            float mn0 = fmaxf(m10, mx0), mn1 = fmaxf(m11, mx1);
            float al0 = fexp(m10 - mn0), al1 = fexp(m11 - mn1);
            float ls0 = 0.f, ls1 = 0.f;
            #pragma unroll
            for (int ni = 0; ni < 8; ni++) {
                float p0 = fexp(s1[ni][0] - mn0);
                float p1 = fexp(s1[ni][1] - mn0);
                float p2 = fexp(s1[ni][2] - mn1);
                float p3 = fexp(s1[ni][3] - mn1);
                ls0 += p0 + p1; ls1 += p2 + p3;
                int cb = (ni * 8 + lm * 2) * 2;
                *(__half2*)(smem + ATT_PS + (q0 + 16 + l4) * 144 + cb) =
                    __floats2half2_rn(p0, p1);
                *(__half2*)(smem + ATT_PS + (q0 + 24 + l4) * 144 + cb) =
                    __floats2half2_rn(p2, p3);
            }
            ls0 += __shfl_xor_sync(0xffffffffu, ls0, 1);
            ls0 += __shfl_xor_sync(0xffffffffu, ls0, 2);
            ls1 += __shfl_xor_sync(0xffffffffu, ls1, 1);
            ls1 += __shfl_xor_sync(0xffffffffu, ls1, 2);
            l10 = l10 * al0 + ls0;  m10 = mn0;
            l11 = l11 * al1 + ls1;  m11 = mn1;
            #pragma unroll
            for (int ni = 0; ni < 16; ni++) {
                O1[ni][0] *= al0; O1[ni][1] *= al0;
                O1[ni][2] *= al1; O1[ni][3] *= al1;
            }
        }
        __syncwarp();          // P stores visible to this warp's ldsm

        // ---- O += P @ V (both subtiles share every V fragment) ----
        const unsigned vbase = sb + ATT_V + slot * 17408 + vtb;
        #pragma unroll
        for (int kp = 0; kp < 4; kp++) {
            unsigned a0[4], a1[4];
            ldsm4(a0, pa + kp * 32);
            ldsm4(a1, pa + 16 * 144 + kp * 32);
            #pragma unroll
            for (int g = 0; g < 8; g++) {
                unsigned bf[4];
                ldsm4t(bf, vbase + kp * 16 * 272 + g * 32);
                mma16(O0[2 * g],     a0, bf[0], bf[2]);
                mma16(O0[2 * g + 1], a0, bf[1], bf[3]);
                mma16(O1[2 * g],     a1, bf[0], bf[2]);
                mma16(O1[2 * g + 1], a1, bf[1], bf[3]);
            }
        }
        // no trailing barrier: next iteration's syncthreads protects reuse
    }

    // epilogue (both subtiles)
    float i00 = 1.0f / l00, i01 = 1.0f / l01;
    float i10 = 1.0f / l10, i11 = 1.0f / l11;
    size_t r0 = (size_t)qt * 192 + q0 + l4;
    __half* op0 = g_o + ((size_t)b * NT + r0) * DIM + h * HD;
    __half* op1 = g_o + ((size_t)b * NT + r0 + 8) * DIM + h * HD;
    __half* op2 = g_o + ((size_t)b * NT + r0 + 16) * DIM + h * HD;
    __half* op3 = g_o + ((size_t)b * NT + r0 + 24) * DIM + h * HD;
    #pragma unroll
    for (int ni = 0; ni < 16; ni++) {
        int cc = ni * 8 + lm * 2;
        *(__half2*)(op0 + cc) = __floats2half2_rn(O0[ni][0] * i00,
                                                  O0[ni][1] * i00);
        *(__half2*)(op1 + cc) = __floats2half2_rn(O0[ni][2] * i01,
                                                  O0[ni][3] * i01);
        *(__half2*)(op2 + cc) = __floats2half2_rn(O1[ni][0] * i10,
                                                  O1[ni][1] * i10);
        *(__half2*)(op3 + cc) = __floats2half2_rn(O1[ni][2] * i11,
                                                  O1[ni][3] * i11);
    }
}

// ------------------------- launch --------------------------------------------
extern "C" void kernel_launch(void* const* d_in, const int* in_sizes, int n_in,
                              void* d_out, int out_size)
{
    (void)in_sizes; (void)n_in; (void)out_size;

    const float* input     = (const float*)d_in[0];
    const float* context   = (const float*)d_in[1];
    const float* W_qkv_in  = (const float*)d_in[2];
    const float* b_qkv_in  = (const float*)d_in[3];
    const float* W_qkv_ctx = (const float*)d_in[4];
    const float* b_qkv_ctx = (const float*)d_in[5];
    const float* qs_in     = (const float*)d_in[6];
    const float* ks_in     = (const float*)d_in[7];
    const float* qs_ctx    = (const float*)d_in[8];
    const float* ks_ctx    = (const float*)d_in[9];
    const float* W_out_in  = (const float*)d_in[10];
    const float* b_out_in  = (const float*)d_in[11];
    const float* W_out_ctx = (const float*)d_in[12];
    const float* b_out_ctx = (const float*)d_in[13];
    float* out = (float*)d_out;

    __half *in_r, *ctx_r;
    cudaGetSymbolAddress((void**)&in_r,  g_in_r);
    cudaGetSymbolAddress((void**)&ctx_r, g_ctx_r);

    cudaFuncSetAttribute(qkv_gemm,
                         cudaFuncAttributeMaxDynamicSharedMemorySize, SM_GEMM);
    cudaFuncSetAttribute(out_gemm,
                         cudaFuncAttributeMaxDynamicSharedMemorySize, SM_GEMM);
    cudaFuncSetAttribute(attn_kernel,
                         cudaFuncAttributeMaxDynamicSharedMemorySize, SM_ATTN);

    // 0) prep: conversions, weight transpose, rope table
    {
        int n40 = BB * S_IN  * DIM / 4;
        int n41 = BB * S_CTX * DIM / 4;
        half_copy2<<<dim3((n40 + 255) / 256, 1, 2), 256>>>(
            input, in_r, n40, context, ctx_r, n41);
    }
    transpose_half4<<<dim3(Q3 / 32, DIM / 32, 4), dim3(32, 8)>>>(
        W_qkv_in, W_qkv_ctx, W_out_in, W_out_ctx);
    rope_table<<<NT, 64>>>();

    // 1) QKV projections (merged, 128x128 CTA tiles)
    qkv_gemm<<<dim3(Q3 / 128, 36), 256, SM_GEMM>>>(b_qkv_in, b_qkv_ctx);

    // 2) RMSNorm + RoPE + scatter
    normrope_kernel<<<dim3(NT, BB), 256>>>(qs_in, ks_in, qs_ctx, ks_ctx);

    // 3) Attention (192-query tiles, 6 warps x 32q)
    attn_kernel<<<dim3(NT / 192, NH, BB), 192, SM_ATTN>>>();

    // 4) Output projections (merged)
    out_gemm<<<dim3(DIM / 128, 36), 256, SM_GEMM>>>(b_out_in, b_out_ctx, out);
}

// round 13
// speedup vs baseline: 1.1369x; 1.0371x over previous
#include <cuda_runtime.h>
#include <cuda_fp16.h>
#include <math.h>
#include <stdint.h>

#define NH    12
#define HD    128
#define DIM   1536
#define BB    2
#define S_IN  2048
#define S_CTX 256
#define NT    (S_IN + S_CTX)   // 2304
#define Q3    (3 * DIM)        // 4608
#define NKT   (NT / 64)        // 36

// ------------------------- scratch (no cudaMalloc allowed) -------------------
static __device__ __half g_qkv_in [(size_t)BB * S_IN  * Q3];
static __device__ __half g_qkv_ctx[(size_t)BB * S_CTX * Q3];
static __device__ __half g_q[(size_t)BB * NH * NT * HD];   // scaled, [b][h][n][d]
static __device__ __half g_k[(size_t)BB * NH * NT * HD];   // [b][h][n][d]
static __device__ __half g_v[(size_t)BB * NH * NT * HD];   // [b][h][n][d]
static __device__ __half g_o[(size_t)BB * NT * DIM];
static __device__ __half g_wt[18874368];                   // transposed weights
static __device__ __half g_in_r [(size_t)BB * S_IN  * DIM];
static __device__ __half g_ctx_r[(size_t)BB * S_CTX * DIM];
static __device__ float2 g_rope[(size_t)NT * 64];          // (cos, sin)

#define WT_QKV_IN  0
#define WT_QKV_CTX 7077888
#define WT_OUT_IN  14155776
#define WT_OUT_CTX 16515072

// ------------------------- helpers -------------------------------------------
__device__ __forceinline__ unsigned smem_u32(const void* p) {
    unsigned a;
    asm("{ .reg .u64 t; cvta.to.shared.u64 t, %1; cvt.u32.u64 %0, t; }"
        : "=r"(a) : "l"(p));
    return a;
}

__device__ __forceinline__ void cp16(unsigned s, const void* g) {
    unsigned long long ga;
    asm("cvta.to.global.u64 %0, %1;" : "=l"(ga) : "l"(g));
    asm volatile("cp.async.cg.shared.global [%0], [%1], 16;"
                 :: "r"(s), "l"(ga));
}
#define CP_COMMIT() asm volatile("cp.async.commit_group;" ::: "memory")
#define CP_WAIT0()  asm volatile("cp.async.wait_group 0;" ::: "memory")
#define CP_WAIT1()  asm volatile("cp.async.wait_group 1;" ::: "memory")
#define CP_WAIT2()  asm volatile("cp.async.wait_group 2;" ::: "memory")

__device__ __forceinline__ void ldsm4(unsigned* r, unsigned addr) {
    asm volatile("ldmatrix.sync.aligned.m8n8.x4.shared.b16 {%0,%1,%2,%3}, [%4];"
        : "=r"(r[0]), "=r"(r[1]), "=r"(r[2]), "=r"(r[3]) : "r"(addr));
}

__device__ __forceinline__ void ldsm4t(unsigned* r, unsigned addr) {
    asm volatile("ldmatrix.sync.aligned.m8n8.x4.trans.shared.b16 {%0,%1,%2,%3}, [%4];"
        : "=r"(r[0]), "=r"(r[1]), "=r"(r[2]), "=r"(r[3]) : "r"(addr));
}

__device__ __forceinline__ void mma16(float* c, const unsigned* a,
                                      unsigned b0, unsigned b1) {
    asm volatile(
        "mma.sync.aligned.m16n8k16.row.col.f32.f16.f16.f32 "
        "{%0,%1,%2,%3}, {%4,%5,%6,%7}, {%8,%9}, {%0,%1,%2,%3};"
        : "+f"(c[0]), "+f"(c[1]), "+f"(c[2]), "+f"(c[3])
        : "r"(a[0]), "r"(a[1]), "r"(a[2]), "r"(a[3]), "r"(b0), "r"(b1));
}

__device__ __forceinline__ float fexp(float x) {
    float r;
    asm("ex2.approx.ftz.f32 %0, %1;" : "=f"(r) : "f"(x * 1.4426950408889634f));
    return r;
}

// ------------------------- merged prep kernels -------------------------------
// z=0: input->half, z=1: context->half, z=2: rope table (guarded)
__global__ void __launch_bounds__(256)
half_copy2(const float* __restrict__ in0, __half* __restrict__ out0, int n40,
           const float* __restrict__ in1, __half* __restrict__ out1, int n41)
{
    if (blockIdx.z == 2) {
        int i = blockIdx.x * 256 + threadIdx.x;
        if (i < NT * 64) {
            int pos = i >> 6, t = i & 63;
            double ang = (double)pos * pow(10000.0, -(double)t / 64.0);
            g_rope[i] = make_float2((float)cos(ang), (float)sin(ang));
        }
        return;
    }
    const float* in = blockIdx.z ? in1 : in0;
    __half* out     = blockIdx.z ? out1 : out0;
    int n4          = blockIdx.z ? n41 : n40;
    int i = blockIdx.x * 256 + threadIdx.x;
    if (i < n4) {
        float4 v = ((const float4*)in)[i];
        ((__half2*)out)[2 * i]     = __floats2half2_rn(v.x, v.y);
        ((__half2*)out)[2 * i + 1] = __floats2half2_rn(v.z, v.w);
    }
}

// W [K=DIM][N] rm -> Wt [N][K] rm (half). z selects which weight.
__global__ void __launch_bounds__(256)
transpose_half4(const float* __restrict__ W0, const float* __restrict__ W1,
                const float* __restrict__ W2, const float* __restrict__ W3)
{
    const float* W; size_t off; int N;
    switch (blockIdx.z) {
        case 0:  W = W0; off = WT_QKV_IN;  N = Q3;  break;
        case 1:  W = W1; off = WT_QKV_CTX; N = Q3;  break;
        case 2:  W = W2; off = WT_OUT_IN;  N = DIM; break;
        default: W = W3; off = WT_OUT_CTX; N = DIM; break;
    }
    if ((int)blockIdx.x * 32 >= N) return;
    __half* Wt = g_wt + off;
    __shared__ float t[32][33];
    int x  = blockIdx.x * 32 + threadIdx.x;   // n
    int y0 = blockIdx.y * 32 + threadIdx.y;   // k
    #pragma unroll
    for (int j = 0; j < 4; j++)
        t[threadIdx.y + j * 8][threadIdx.x] = W[(size_t)(y0 + j * 8) * N + x];
    __syncthreads();
    int x2 = blockIdx.y * 32 + threadIdx.x;   // k
    int y2 = blockIdx.x * 32 + threadIdx.y;   // n
    #pragma unroll
    for (int j = 0; j < 4; j++)
        Wt[(size_t)(y2 + j * 8) * DIM + x2] =
            __float2half_rn(t[threadIdx.x][threadIdx.y + j * 8]);
}

// ------------------------- F16 GEMM core (R10 config) ------------------------
// CTA tile 128x128, warp tile 64x32, k-chunk 32, 4-stage cp.async ring.
// 20.5 KB/stage -> 82 KB total -> 2 CTAs/SM (16 warps).
#define G_STAGE 20480
#define SM_GEMM (4 * G_STAGE)

__device__ __forceinline__ void gstore(__half* p, float x, float y) {
    *(__half2*)p = __floats2half2_rn(x, y);
}
__device__ __forceinline__ void gstore(float* p, float x, float y) {
    *(float2*)p = make_float2(x, y);
}

template <typename OutT>
__device__ __forceinline__ void gemm_core(
    const __half* __restrict__ Ap, const __half* __restrict__ Wp,
    const float* __restrict__ bp, OutT* __restrict__ Cp,
    int K, int N, char* smem)
{
    const unsigned sb = smem_u32(smem);
    const int tid  = threadIdx.x;
    const int lane = tid & 31;
    const int wid  = tid >> 5;
    const int wm   = (wid & 1) * 64;
    const int wn   = (wid >> 1) * 32;
    const int l4   = lane >> 2;
    const int lm   = lane & 3;
    const int NCH  = K / 32;

    const int lrow = tid >> 1;            // 0..127
    const int lcb  = (tid & 1) * 32;      // byte offset within 64B row
    auto issue = [&](int c, int st) {
        unsigned as = sb + st * G_STAGE;
        unsigned bs = as + 10240;
        const __half* ag = Ap + (size_t)lrow * K + c * 32 + lcb / 2;
        cp16(as + lrow * 80 + lcb, ag);
        cp16(as + lrow * 80 + lcb + 16, ag + 8);
        const __half* bg = Wp + (size_t)lrow * K + c * 32 + lcb / 2;
        cp16(bs + lrow * 80 + lcb, bg);
        cp16(bs + lrow * 80 + lcb + 16, bg + 8);
    };

    float acc[4][4][4];
    #pragma unroll
    for (int mi = 0; mi < 4; mi++)
        #pragma unroll
        for (int ni = 0; ni < 4; ni++)
            #pragma unroll
            for (int c = 0; c < 4; c++) acc[mi][ni][c] = 0.f;

    issue(0, 0); CP_COMMIT();
    issue(1, 1); CP_COMMIT();
    issue(2, 2); CP_COMMIT();

    const unsigned a_off = (wm + (lane & 15)) * 80 + (lane >> 4) * 16;
    const unsigned b_off = 10240 + (wn + (lane & 15)) * 80 + (lane >> 4) * 16;

    for (int i = 0; i < NCH; i++) {
        CP_WAIT2();
        __syncthreads();
        if (i + 3 < NCH) issue(i + 3, (i + 3) & 3);
        CP_COMMIT();

        unsigned st = sb + (i & 3) * G_STAGE;
        #pragma unroll
        for (int kp = 0; kp < 2; kp++) {
            unsigned af[4][4];
            #pragma unroll
            for (int mi = 0; mi < 4; mi++)
                ldsm4(af[mi], st + a_off + mi * 16 * 80 + kp * 32);
            #pragma unroll
            for (int nb = 0; nb < 2; nb++) {
                unsigned bf[4];
                ldsm4(bf, st + b_off + nb * 16 * 80 + kp * 32);
                #pragma unroll
                for (int mi = 0; mi < 4; mi++) {
                    mma16(acc[mi][2 * nb],     af[mi], bf[0], bf[2]);
                    mma16(acc[mi][2 * nb + 1], af[mi], bf[1], bf[3]);
                }
            }
        }
    }

    #pragma unroll
    for (int mi = 0; mi < 4; mi++) {
        #pragma unroll
        for (int ni = 0; ni < 4; ni++) {
            int r0 = wm + 16 * mi + l4;
            int c0 = wn + 8 * ni + 2 * lm;
            float bx = bp[c0], by = bp[c0 + 1];
            gstore(Cp + (size_t)r0 * N + c0,
                   acc[mi][ni][0] + bx, acc[mi][ni][1] + by);
            gstore(Cp + (size_t)(r0 + 8) * N + c0,
                   acc[mi][ni][2] + bx, acc[mi][ni][3] + by);
        }
    }
}

// merged QKV projections: y<32 -> input rows, y>=32 -> ctx rows
__global__ void __launch_bounds__(256, 2)
qkv_gemm(const float* __restrict__ b_in, const float* __restrict__ b_ctx)
{
    extern __shared__ char smem[];
    int y = blockIdx.y;
    const __half* A; const __half* W; const float* bias; __half* C;
    if (y < 32) {
        A = g_in_r + (size_t)y * 128 * DIM;
        W = g_wt + WT_QKV_IN;  bias = b_in;
        C = g_qkv_in + (size_t)y * 128 * Q3;
    } else {
        int y2 = y - 32;
        A = g_ctx_r + (size_t)y2 * 128 * DIM;
        W = g_wt + WT_QKV_CTX; bias = b_ctx;
        C = g_qkv_ctx + (size_t)y2 * 128 * Q3;
    }
    gemm_core<__half>(A, W + (size_t)blockIdx.x * 128 * DIM,
                      bias + blockIdx.x * 128, C + blockIdx.x * 128,
                      DIM, Q3, smem);
}

// merged output projections: y<32 -> input part (b = y>>4), else ctx part
__global__ void __launch_bounds__(256, 2)
out_gemm(const float* __restrict__ b_in, const float* __restrict__ b_ctx,
         float* __restrict__ out)
{
    extern __shared__ char smem[];
    int y = blockIdx.y;
    const __half* A; const __half* W; const float* bias; float* C;
    if (y < 32) {
        int b = y >> 4, yy = y & 15;
        A = g_o + ((size_t)b * NT + S_CTX + yy * 128) * DIM;
        W = g_wt + WT_OUT_IN;  bias = b_in;
        C = out + ((size_t)b * S_IN + yy * 128) * DIM;
    } else {
        int z = y - 32, b = z >> 1, yy = z & 1;
        A = g_o + ((size_t)b * NT + yy * 128) * DIM;
        W = g_wt + WT_OUT_CTX; bias = b_ctx;
        C = out + (size_t)BB * S_IN * DIM + ((size_t)b * S_CTX + yy * 128) * DIM;
    }
    gemm_core<float>(A, W + (size_t)blockIdx.x * 128 * DIM,
                     bias + blockIdx.x * 128, C + blockIdx.x * 128,
                     DIM, DIM, smem);
}

// ----------------- RMSNorm + RoPE + scatter (half -> half) -------------------
// 512 threads: lower half normalizes Q, upper half normalizes K in parallel.
// Only TWO __syncthreads total.
__global__ void __launch_bounds__(512)
normrope_kernel(const float* __restrict__ qs_in, const float* __restrict__ ks_in,
                const float* __restrict__ qs_ctx, const float* __restrict__ ks_ctx)
{
    const int pos  = blockIdx.x;
    const int b    = blockIdx.y;
    const int tid  = threadIdx.x;
    const int half = tid >> 8;        // 0 = Q, 1 = K
    const int t    = tid & 255;

    __shared__ float buf[2][DIM];
    __shared__ float red[16];
    __shared__ float cosv[64], sinv[64];

    const __half* src; const float* qs; const float* ks;
    if (pos < S_CTX) {
        src = g_qkv_ctx + ((size_t)b * S_CTX + pos) * Q3;
        qs = qs_ctx; ks = ks_ctx;
    } else {
        src = g_qkv_in + ((size_t)b * S_IN + (pos - S_CTX)) * Q3;
        qs = qs_in; ks = ks_in;
    }

    if (tid < 64) {
        float2 cs = g_rope[(size_t)pos * 64 + tid];
        cosv[tid] = cs.x;
        sinv[tid] = cs.y;
    }

    const float qscale = 0.088388347648318447f;   // 128^-0.5

    const __half* x  = src + half * DIM;
    const float*  sc = half ? ks : qs;
    float v[6];
    float local = 0.f;
    #pragma unroll
    for (int i = 0; i < 6; i++) {
        v[i] = __half2float(x[t + i * 256]);
        local = fmaf(v[i], v[i], local);
    }
    #pragma unroll
    for (int off = 16; off; off >>= 1)
        local += __shfl_xor_sync(0xffffffffu, local, off);
    if ((tid & 31) == 0) red[tid >> 5] = local;
    __syncthreads();

    float tot = 0.f;
    #pragma unroll
    for (int j = 0; j < 8; j++) tot += red[half * 8 + j];
    float r = rsqrtf(tot * (1.0f / DIM) + 1e-6f);
    #pragma unroll
    for (int i = 0; i < 6; i++)
        buf[half][t + i * 256] = v[i] * r * sc[t + i * 256];
    __syncthreads();

    __half* dst = half ? g_k : g_q;
    float post = half ? 1.0f : qscale;
    #pragma unroll
    for (int i = 0; i < 6; i++) {
        int e = t + i * 256;
        int hh = e >> 7, d = e & 127, j = d & 63;
        float c = cosv[j], sn = sinv[j];
        float y = (d < 64) ? (buf[half][e] * c - buf[half][e + 64] * sn)
                           : (buf[half][e] * c + buf[half][e - 64] * sn);
        dst[(((size_t)b * NH + hh) * NT + pos) * HD + d] =
            __float2half_rn(y * post);
    }

    // V: copy to [b][h][n][d] (3 elems per thread, coalesced per head)
    #pragma unroll
    for (int i = 0; i < 3; i++) {
        int e = tid + i * 512;
        int hh = e >> 7, d = e & 127;
        g_v[(((size_t)b * NH + hh) * NT + pos) * HD + d] = src[2 * DIM + e];
    }
}

// ------------------------- F16 flash attention (R10 config) ------------------
// 192-query tile, 384 thr / 12 warps x 16q. K+V triple-buffered together (one
// commit group per ktile) -> ONE __syncthreads + one wait per ktile.
// V row-major; PV B-fragments via ldmatrix.trans. P warp-private.
// Smem: Qs 192x272 | K 3x(64x272) | V 3x(64x272) | Ps 192x144
#define ATT_QS   0
#define ATT_K    52224
#define ATT_V    104448
#define ATT_PS   156672
#define SM_ATTN  184320

__global__ void __launch_bounds__(384, 1)
attn_kernel(void)
{
    extern __shared__ char smem[];
    const unsigned sb = smem_u32(smem);

    const int qt = blockIdx.x, h = blockIdx.y, b = blockIdx.z;
    const size_t base = (((size_t)b * NH + h) * NT) * HD;
    const __half* Qg = g_q + base + (size_t)qt * 192 * HD;
    const __half* Kg = g_k + base;
    const __half* Vg = g_v + base;

    const int tid  = threadIdx.x;
    const int lane = tid & 31;
    const int wid  = tid >> 5;        // 0..11
    const int l4   = lane >> 2;
    const int lm   = lane & 3;
    const int q0   = wid * 16;

    auto load_KV = [&](int kt, int slot) {
        unsigned kdst = sb + ATT_K + slot * 17408;
        unsigned vdst = sb + ATT_V + slot * 17408;
        const __half* ks = Kg + (size_t)kt * 64 * HD;
        const __half* vs = Vg + (size_t)kt * 64 * HD;
        for (int lin = tid; lin < 1024; lin += 384) {
            int row = lin >> 4, ch = lin & 15;
            cp16(kdst + row * 272 + ch * 16, ks + row * 128 + ch * 8);
            cp16(vdst + row * 272 + ch * 16, vs + row * 128 + ch * 8);
        }
    };

    // prologue: Q (group 0), KV0 (group 1), KV1 (group 2)
    for (int lin = tid; lin < 3072; lin += 384) {
        int row = lin >> 4, ch = lin & 15;
        cp16(sb + ATT_QS + row * 272 + ch * 16, Qg + row * 128 + ch * 8);
    }
    CP_COMMIT();
    load_KV(0, 0); CP_COMMIT();
    load_KV(1, 1); CP_COMMIT();

    float O[16][4];
    #pragma unroll
    for (int ni = 0; ni < 16; ni++)
        #pragma unroll
        for (int c = 0; c < 4; c++) O[ni][c] = 0.f;
    float m0 = -1e30f, m1 = -1e30f, l0 = 0.f, l1 = 0.f;

    const unsigned qa = sb + ATT_QS + (q0 + (lane & 15)) * 272 + (lane >> 4) * 16;
    const unsigned kb = (lane & 15) * 272 + (lane >> 4) * 16;
    const unsigned pa = sb + ATT_PS + (q0 + (lane & 15)) * 144 + (lane >> 4) * 16;
    const unsigned vtb = ((lane & 7) + ((lane >> 4) << 3)) * 272
                       + ((lane >> 3) & 1) * 16;

    for (int kt = 0; kt < NKT; kt++) {
        const int slot = kt % 3;
        CP_WAIT1();            // Q + KV(kt) resident
        __syncthreads();       // slot (kt+2)%3 readers (iter kt-1) done
        if (kt + 2 < NKT) load_KV(kt + 2, (kt + 2) % 3);
        CP_COMMIT();

        // ---- S = Q @ K^T ----
        const unsigned kbase = sb + ATT_K + slot * 17408 + kb;
        float s[8][4];
        #pragma unroll
        for (int ni = 0; ni < 8; ni++)
            #pragma unroll
            for (int c = 0; c < 4; c++) s[ni][c] = 0.f;

        #pragma unroll
        for (int kp = 0; kp < 8; kp++) {
            unsigned a[4];
            ldsm4(a, qa + kp * 32);
            #pragma unroll
            for (int nb = 0; nb < 4; nb++) {
                unsigned bf[4];
                ldsm4(bf, kbase + nb * 16 * 272 + kp * 32);
                mma16(s[2 * nb],     a, bf[0], bf[2]);
                mma16(s[2 * nb + 1], a, bf[1], bf[3]);
            }
        }

        // ---- online softmax (rows are warp-private) ----
        float mx0 = -1e30f, mx1 = -1e30f;
        #pragma unroll
        for (int ni = 0; ni < 8; ni++) {
            mx0 = fmaxf(mx0, fmaxf(s[ni][0], s[ni][1]));
            mx1 = fmaxf(mx1, fmaxf(s[ni][2], s[ni][3]));
        }
        mx0 = fmaxf(mx0, __shfl_xor_sync(0xffffffffu, mx0, 1));
        mx0 = fmaxf(mx0, __shfl_xor_sync(0xffffffffu, mx0, 2));
        mx1 = fmaxf(mx1, __shfl_xor_sync(0xffffffffu, mx1, 1));
        mx1 = fmaxf(mx1, __shfl_xor_sync(0xffffffffu, mx1, 2));

        float mn0 = fmaxf(m0, mx0), mn1 = fmaxf(m1, mx1);
        float al0 = fexp(m0 - mn0), al1 = fexp(m1 - mn1);
        float ls0 = 0.f, ls1 = 0.f;
        #pragma unroll
        for (int ni = 0; ni < 8; ni++) {
            float p0 = fexp(s[ni][0] - mn0);
            float p1 = fexp(s[ni][1] - mn0);
            float p2 = fexp(s[ni][2] - mn1);
            float p3 = fexp(s[ni][3] - mn1);
            ls0 += p0 + p1; ls1 += p2 + p3;
            int cb = (ni * 8 + lm * 2) * 2;
            *(__half2*)(smem + ATT_PS + (q0 + l4) * 144 + cb) =
                __floats2half2_rn(p0, p1);
            *(__half2*)(smem + ATT_PS + (q0 + l4 + 8) * 144 + cb) =
                __floats2half2_rn(p2, p3);
        }
        ls0 += __shfl_xor_sync(0xffffffffu, ls0, 1);
        ls0 += __shfl_xor_sync(0xffffffffu, ls0, 2);
        ls1 += __shfl_xor_sync(0xffffffffu, ls1, 1);
        ls1 += __shfl_xor_sync(0xffffffffu, ls1, 2);
        l0 = l0 * al0 + ls0;  m0 = mn0;
        l1 = l1 * al1 + ls1;  m1 = mn1;
        #pragma unroll
        for (int ni = 0; ni < 16; ni++) {
            O[ni][0] *= al0; O[ni][1] *= al0;
            O[ni][2] *= al1; O[ni][3] *= al1;
        }
        __syncwarp();          // P stores visible to this warp's ldsm

        // ---- O += P @ V (V row-major, trans ldmatrix) ----
        const unsigned vbase = sb + ATT_V + slot * 17408 + vtb;
        #pragma unroll
        for (int kp = 0; kp < 4; kp++) {
            unsigned a[4];
            ldsm4(a, pa + kp * 32);
            #pragma unroll
            for (int g = 0; g < 8; g++) {
                unsigned bf[4];
                ldsm4t(bf, vbase + kp * 16 * 272 + g * 32);
                mma16(O[2 * g],     a, bf[0], bf[2]);
                mma16(O[2 * g + 1], a, bf[1], bf[3]);
            }
        }
        // no trailing barrier: next iteration's syncthreads protects reuse
    }

    // epilogue
    float inv0 = 1.0f / l0, inv1 = 1.0f / l1;
    size_t r0 = (size_t)qt * 192 + q0 + l4;
    __half* op0 = g_o + ((size_t)b * NT + r0) * DIM + h * HD;
    __half* op1 = g_o + ((size_t)b * NT + r0 + 8) * DIM + h * HD;
    #pragma unroll
    for (int ni = 0; ni < 16; ni++) {
        int cc = ni * 8 + lm * 2;
        *(__half2*)(op0 + cc) = __floats2half2_rn(O[ni][0] * inv0,
                                                  O[ni][1] * inv0);
        *(__half2*)(op1 + cc) = __floats2half2_rn(O[ni][2] * inv1,
                                                  O[ni][3] * inv1);
    }
}

// ------------------------- launch --------------------------------------------
extern "C" void kernel_launch(void* const* d_in, const int* in_sizes, int n_in,
                              void* d_out, int out_size)
{
    (void)in_sizes; (void)n_in; (void)out_size;

    const float* input     = (const float*)d_in[0];
    const float* context   = (const float*)d_in[1];
    const float* W_qkv_in  = (const float*)d_in[2];
    const float* b_qkv_in  = (const float*)d_in[3];
    const float* W_qkv_ctx = (const float*)d_in[4];
    const float* b_qkv_ctx = (const float*)d_in[5];
    const float* qs_in     = (const float*)d_in[6];
    const float* ks_in     = (const float*)d_in[7];
    const float* qs_ctx    = (const float*)d_in[8];
    const float* ks_ctx    = (const float*)d_in[9];
    const float* W_out_in  = (const float*)d_in[10];
    const float* b_out_in  = (const float*)d_in[11];
    const float* W_out_ctx = (const float*)d_in[12];
    const float* b_out_ctx = (const float*)d_in[13];
    float* out = (float*)d_out;

    __half *in_r, *ctx_r;
    cudaGetSymbolAddress((void**)&in_r,  g_in_r);
    cudaGetSymbolAddress((void**)&ctx_r, g_ctx_r);

    cudaFuncSetAttribute(qkv_gemm,
                         cudaFuncAttributeMaxDynamicSharedMemorySize, SM_GEMM);
    cudaFuncSetAttribute(out_gemm,
                         cudaFuncAttributeMaxDynamicSharedMemorySize, SM_GEMM);
    cudaFuncSetAttribute(attn_kernel,
                         cudaFuncAttributeMaxDynamicSharedMemorySize, SM_ATTN);

    // 0) prep: conversions + rope table (z=2), weight transpose
    {
        int n40 = BB * S_IN  * DIM / 4;
        int n41 = BB * S_CTX * DIM / 4;
        half_copy2<<<dim3((n40 + 255) / 256, 1, 3), 256>>>(
            input, in_r, n40, context, ctx_r, n41);
    }
    transpose_half4<<<dim3(Q3 / 32, DIM / 32, 4), dim3(32, 8)>>>(
        W_qkv_in, W_qkv_ctx, W_out_in, W_out_ctx);

    // 1) QKV projections (merged, 128x128 CTA tiles)
    qkv_gemm<<<dim3(Q3 / 128, 36), 256, SM_GEMM>>>(b_qkv_in, b_qkv_ctx);

    // 2) RMSNorm + RoPE + scatter (512 thr: Q and K in parallel)
    normrope_kernel<<<dim3(NT, BB), 512>>>(qs_in, ks_in, qs_ctx, ks_ctx);

    // 3) Attention (192-query tiles, 12 warps x 16q)
    attn_kernel<<<dim3(NT / 192, NH, BB), 384, SM_ATTN>>>();

    // 4) Output projections (merged)
    out_gemm<<<dim3(DIM / 128, 36), 256, SM_GEMM>>>(b_out_in, b_out_ctx, out);
}

// round 14
// speedup vs baseline: 1.1969x; 1.0527x over previous
#include <cuda_runtime.h>
#include <cuda_fp16.h>
#include <math.h>
#include <stdint.h>

#define NH    12
#define HD    128
#define DIM   1536
#define BB    2
#define S_IN  2048
#define S_CTX 256
#define NT    (S_IN + S_CTX)   // 2304
#define Q3    (3 * DIM)        // 4608
#define NKT   (NT / 64)        // 36

// ------------------------- scratch (no cudaMalloc allowed) -------------------
static __device__ __half g_qkv_in [(size_t)BB * S_IN  * Q3];
static __device__ __half g_qkv_ctx[(size_t)BB * S_CTX * Q3];
static __device__ __half g_q[(size_t)BB * NH * NT * HD];   // scaled, [b][h][n][d]
static __device__ __half g_k[(size_t)BB * NH * NT * HD];   // [b][h][n][d]
static __device__ __half g_v[(size_t)BB * NH * NT * HD];   // [b][h][n][d]
static __device__ __half g_o[(size_t)BB * NT * DIM];
static __device__ __half g_wt[18874368];                   // transposed weights
static __device__ __half g_in_r [(size_t)BB * S_IN  * DIM];
static __device__ __half g_ctx_r[(size_t)BB * S_CTX * DIM];
static __device__ float2 g_rope[(size_t)NT * 64];          // (cos, sin)

#define WT_QKV_IN  0
#define WT_QKV_CTX 7077888
#define WT_OUT_IN  14155776
#define WT_OUT_CTX 16515072

// ------------------------- helpers -------------------------------------------
__device__ __forceinline__ unsigned smem_u32(const void* p) {
    unsigned a;
    asm("{ .reg .u64 t; cvta.to.shared.u64 t, %1; cvt.u32.u64 %0, t; }"
        : "=r"(a) : "l"(p));
    return a;
}

__device__ __forceinline__ void cp16(unsigned s, const void* g) {
    unsigned long long ga;
    asm("cvta.to.global.u64 %0, %1;" : "=l"(ga) : "l"(g));
    asm volatile("cp.async.cg.shared.global [%0], [%1], 16;"
                 :: "r"(s), "l"(ga));
}
#define CP_COMMIT() asm volatile("cp.async.commit_group;" ::: "memory")
#define CP_WAIT0()  asm volatile("cp.async.wait_group 0;" ::: "memory")
#define CP_WAIT1()  asm volatile("cp.async.wait_group 1;" ::: "memory")
#define CP_WAIT2()  asm volatile("cp.async.wait_group 2;" ::: "memory")

__device__ __forceinline__ void ldsm4(unsigned* r, unsigned addr) {
    asm volatile("ldmatrix.sync.aligned.m8n8.x4.shared.b16 {%0,%1,%2,%3}, [%4];"
        : "=r"(r[0]), "=r"(r[1]), "=r"(r[2]), "=r"(r[3]) : "r"(addr));
}

__device__ __forceinline__ void ldsm4t(unsigned* r, unsigned addr) {
    asm volatile("ldmatrix.sync.aligned.m8n8.x4.trans.shared.b16 {%0,%1,%2,%3}, [%4];"
        : "=r"(r[0]), "=r"(r[1]), "=r"(r[2]), "=r"(r[3]) : "r"(addr));
}

__device__ __forceinline__ void mma16(float* c, const unsigned* a,
                                      unsigned b0, unsigned b1) {
    asm volatile(
        "mma.sync.aligned.m16n8k16.row.col.f32.f16.f16.f32 "
        "{%0,%1,%2,%3}, {%4,%5,%6,%7}, {%8,%9}, {%0,%1,%2,%3};"
        : "+f"(c[0]), "+f"(c[1]), "+f"(c[2]), "+f"(c[3])
        : "r"(a[0]), "r"(a[1]), "r"(a[2]), "r"(a[3]), "r"(b0), "r"(b1));
}

__device__ __forceinline__ float fexp(float x) {
    float r;
    asm("ex2.approx.ftz.f32 %0, %1;" : "=f"(r) : "f"(x * 1.4426950408889634f));
    return r;
}

// ------------------------- ONE merged prep kernel ----------------------------
// z=0: input->half (6144 blocks), z=1: context->half (768), z=2: rope (576),
// z=3..6: weight transposes (6912/6912/2304/2304). 256 threads each.
__global__ void __launch_bounds__(256)
prep_kernel(const float* __restrict__ input, const float* __restrict__ context,
            const float* __restrict__ W0, const float* __restrict__ W1,
            const float* __restrict__ W2, const float* __restrict__ W3)
{
    const int z = blockIdx.z;
    if (z == 2) {                       // rope table
        int i = blockIdx.x * 256 + threadIdx.x;
        if (i < NT * 64) {
            int pos = i >> 6, t = i & 63;
            double ang = (double)pos * pow(10000.0, -(double)t / 64.0);
            g_rope[i] = make_float2((float)cos(ang), (float)sin(ang));
        }
        return;
    }
    if (z < 2) {                        // fp32 -> half copies
        const float* in = z ? context : input;
        __half* out     = z ? g_ctx_r : g_in_r;
        int n4          = (z ? BB * S_CTX * DIM : BB * S_IN * DIM) / 4;
        int i = blockIdx.x * 256 + threadIdx.x;
        if (i < n4) {
            float4 v = ((const float4*)in)[i];
            ((__half2*)out)[2 * i]     = __floats2half2_rn(v.x, v.y);
            ((__half2*)out)[2 * i + 1] = __floats2half2_rn(v.z, v.w);
        }
        return;
    }
    // transposes: W [DIM][N] -> Wt [N][DIM]
    const float* W; size_t off; int N;
    switch (z) {
        case 3:  W = W0; off = WT_QKV_IN;  N = Q3;  break;
        case 4:  W = W1; off = WT_QKV_CTX; N = Q3;  break;
        case 5:  W = W2; off = WT_OUT_IN;  N = DIM; break;
        default: W = W3; off = WT_OUT_CTX; N = DIM; break;
    }
    const int nx = N / 32;
    const int bx = blockIdx.x % nx;
    const int by = blockIdx.x / nx;
    if (by >= DIM / 32) return;
    __half* Wt = g_wt + off;
    __shared__ float t[32][33];
    const int tx = threadIdx.x & 31, ty = threadIdx.x >> 5;
    int x  = bx * 32 + tx;              // n
    int y0 = by * 32 + ty;              // k
    #pragma unroll
    for (int j = 0; j < 4; j++)
        t[ty + j * 8][tx] = W[(size_t)(y0 + j * 8) * N + x];
    __syncthreads();
    int x2 = by * 32 + tx;              // k
    int y2 = bx * 32 + ty;              // n
    #pragma unroll
    for (int j = 0; j < 4; j++)
        Wt[(size_t)(y2 + j * 8) * DIM + x2] =
            __float2half_rn(t[tx][ty + j * 8]);
}

// ------------------------- F16 GEMM core (R10 config) ------------------------
// CTA tile 128x128, warp tile 64x32, k-chunk 32, 4-stage cp.async ring.
#define G_STAGE 20480
#define SM_GEMM (4 * G_STAGE)

__device__ __forceinline__ void gstore(__half* p, float x, float y) {
    *(__half2*)p = __floats2half2_rn(x, y);
}
__device__ __forceinline__ void gstore(float* p, float x, float y) {
    *(float2*)p = make_float2(x, y);
}

template <typename OutT>
__device__ __forceinline__ void gemm_core(
    const __half* __restrict__ Ap, const __half* __restrict__ Wp,
    const float* __restrict__ bp, OutT* __restrict__ Cp,
    int K, int N, char* smem)
{
    const unsigned sb = smem_u32(smem);
    const int tid  = threadIdx.x;
    const int lane = tid & 31;
    const int wid  = tid >> 5;
    const int wm   = (wid & 1) * 64;
    const int wn   = (wid >> 1) * 32;
    const int l4   = lane >> 2;
    const int lm   = lane & 3;
    const int NCH  = K / 32;

    const int lrow = tid >> 1;
    const int lcb  = (tid & 1) * 32;
    auto issue = [&](int c, int st) {
        unsigned as = sb + st * G_STAGE;
        unsigned bs = as + 10240;
        const __half* ag = Ap + (size_t)lrow * K + c * 32 + lcb / 2;
        cp16(as + lrow * 80 + lcb, ag);
        cp16(as + lrow * 80 + lcb + 16, ag + 8);
        const __half* bg = Wp + (size_t)lrow * K + c * 32 + lcb / 2;
        cp16(bs + lrow * 80 + lcb, bg);
        cp16(bs + lrow * 80 + lcb + 16, bg + 8);
    };

    float acc[4][4][4];
    #pragma unroll
    for (int mi = 0; mi < 4; mi++)
        #pragma unroll
        for (int ni = 0; ni < 4; ni++)
            #pragma unroll
            for (int c = 0; c < 4; c++) acc[mi][ni][c] = 0.f;

    issue(0, 0); CP_COMMIT();
    issue(1, 1); CP_COMMIT();
    issue(2, 2); CP_COMMIT();

    const unsigned a_off = (wm + (lane & 15)) * 80 + (lane >> 4) * 16;
    const unsigned b_off = 10240 + (wn + (lane & 15)) * 80 + (lane >> 4) * 16;

    for (int i = 0; i < NCH; i++) {
        CP_WAIT2();
        __syncthreads();
        if (i + 3 < NCH) issue(i + 3, (i + 3) & 3);
        CP_COMMIT();

        unsigned st = sb + (i & 3) * G_STAGE;
        #pragma unroll
        for (int kp = 0; kp < 2; kp++) {
            unsigned af[4][4];
            #pragma unroll
            for (int mi = 0; mi < 4; mi++)
                ldsm4(af[mi], st + a_off + mi * 16 * 80 + kp * 32);
            #pragma unroll
            for (int nb = 0; nb < 2; nb++) {
                unsigned bf[4];
                ldsm4(bf, st + b_off + nb * 16 * 80 + kp * 32);
                #pragma unroll
                for (int mi = 0; mi < 4; mi++) {
                    mma16(acc[mi][2 * nb],     af[mi], bf[0], bf[2]);
                    mma16(acc[mi][2 * nb + 1], af[mi], bf[1], bf[3]);
                }
            }
        }
    }

    #pragma unroll
    for (int mi = 0; mi < 4; mi++) {
        #pragma unroll
        for (int ni = 0; ni < 4; ni++) {
            int r0 = wm + 16 * mi + l4;
            int c0 = wn + 8 * ni + 2 * lm;
            float bx = bp[c0], by = bp[c0 + 1];
            gstore(Cp + (size_t)r0 * N + c0,
                   acc[mi][ni][0] + bx, acc[mi][ni][1] + by);
            gstore(Cp + (size_t)(r0 + 8) * N + c0,
                   acc[mi][ni][2] + bx, acc[mi][ni][3] + by);
        }
    }
}

// merged QKV projections
__global__ void __launch_bounds__(256, 2)
qkv_gemm(const float* __restrict__ b_in, const float* __restrict__ b_ctx)
{
    extern __shared__ char smem[];
    int y = blockIdx.y;
    const __half* A; const __half* W; const float* bias; __half* C;
    if (y < 32) {
        A = g_in_r + (size_t)y * 128 * DIM;
        W = g_wt + WT_QKV_IN;  bias = b_in;
        C = g_qkv_in + (size_t)y * 128 * Q3;
    } else {
        int y2 = y - 32;
        A = g_ctx_r + (size_t)y2 * 128 * DIM;
        W = g_wt + WT_QKV_CTX; bias = b_ctx;
        C = g_qkv_ctx + (size_t)y2 * 128 * Q3;
    }
    gemm_core<__half>(A, W + (size_t)blockIdx.x * 128 * DIM,
                      bias + blockIdx.x * 128, C + blockIdx.x * 128,
                      DIM, Q3, smem);
}

// merged output projections
__global__ void __launch_bounds__(256, 2)
out_gemm(const float* __restrict__ b_in, const float* __restrict__ b_ctx,
         float* __restrict__ out)
{
    extern __shared__ char smem[];
    int y = blockIdx.y;
    const __half* A; const __half* W; const float* bias; float* C;
    if (y < 32) {
        int b = y >> 4, yy = y & 15;
        A = g_o + ((size_t)b * NT + S_CTX + yy * 128) * DIM;
        W = g_wt + WT_OUT_IN;  bias = b_in;
        C = out + ((size_t)b * S_IN + yy * 128) * DIM;
    } else {
        int z = y - 32, b = z >> 1, yy = z & 1;
        A = g_o + ((size_t)b * NT + yy * 128) * DIM;
        W = g_wt + WT_OUT_CTX; bias = b_ctx;
        C = out + (size_t)BB * S_IN * DIM + ((size_t)b * S_CTX + yy * 128) * DIM;
    }
    gemm_core<float>(A, W + (size_t)blockIdx.x * 128 * DIM,
                     bias + blockIdx.x * 128, C + blockIdx.x * 128,
                     DIM, DIM, smem);
}

// ----------------- RMSNorm + RoPE + scatter (vectorized half2) ---------------
// 512 threads: lower half handles Q, upper half K. All traffic in 4B+ units.
__global__ void __launch_bounds__(512)
normrope_kernel(const float* __restrict__ qs_in, const float* __restrict__ ks_in,
                const float* __restrict__ qs_ctx, const float* __restrict__ ks_ctx)
{
    const int pos  = blockIdx.x;
    const int b    = blockIdx.y;
    const int tid  = threadIdx.x;
    const int half = tid >> 8;        // 0 = Q, 1 = K
    const int t    = tid & 255;       // pair-lane 0..255 (768 pairs per row)

    __shared__ float2 buf[2][DIM / 2];
    __shared__ float  red[16];
    __shared__ float  cosv[64], sinv[64];

    const __half* src; const float* qs; const float* ks;
    if (pos < S_CTX) {
        src = g_qkv_ctx + ((size_t)b * S_CTX + pos) * Q3;
        qs = qs_ctx; ks = ks_ctx;
    } else {
        src = g_qkv_in + ((size_t)b * S_IN + (pos - S_CTX)) * Q3;
        qs = qs_in; ks = ks_in;
    }

    if (tid < 64) {
        float2 cs = g_rope[(size_t)pos * 64 + tid];
        cosv[tid] = cs.x;
        sinv[tid] = cs.y;
    }

    const float qscale = 0.088388347648318447f;   // 128^-0.5

    const __half2* x2 = (const __half2*)(src + half * DIM);
    const float2*  s2 = (const float2*)(half ? ks : qs);
    float2 v[3];
    float local = 0.f;
    #pragma unroll
    for (int i = 0; i < 3; i++) {
        v[i] = __half22float2(x2[t + i * 256]);
        local = fmaf(v[i].x, v[i].x, fmaf(v[i].y, v[i].y, local));
    }
    #pragma unroll
    for (int off = 16; off; off >>= 1)
        local += __shfl_xor_sync(0xffffffffu, local, off);
    if ((tid & 31) == 0) red[tid >> 5] = local;
    __syncthreads();

    float tot = 0.f;
    #pragma unroll
    for (int j = 0; j < 8; j++) tot += red[half * 8 + j];
    float r = rsqrtf(tot * (1.0f / DIM) + 1e-6f);
    #pragma unroll
    for (int i = 0; i < 3; i++) {
        float2 sc = s2[t + i * 256];
        buf[half][t + i * 256] = make_float2(v[i].x * r * sc.x,
                                             v[i].y * r * sc.y);
    }
    __syncthreads();

    __half* dst = half ? g_k : g_q;
    float post = half ? 1.0f : qscale;
    #pragma unroll
    for (int i = 0; i < 3; i++) {
        int p  = t + i * 256;          // pair index; element e = 2p
        int e  = p * 2;
        int hh = e >> 7, d = e & 127;
        int j  = d & 63;               // pair covers (j, j+1), both same half
        float c0 = cosv[j],     sn0 = sinv[j];
        float c1 = cosv[j + 1], sn1 = sinv[j + 1];
        float2 a  = buf[half][p];
        float2 pr = buf[half][(d < 64) ? (p + 32) : (p - 32)];
        float y0, y1;
        if (d < 64) { y0 = a.x * c0 - pr.x * sn0; y1 = a.y * c1 - pr.y * sn1; }
        else        { y0 = a.x * c0 + pr.x * sn0; y1 = a.y * c1 + pr.y * sn1; }
        *(__half2*)(dst + (((size_t)b * NH + hh) * NT + pos) * HD + d) =
            __floats2half2_rn(y0 * post, y1 * post);
    }

    // V: pair copy to [b][h][n][d]
    const __half2* v2 = (const __half2*)(src + 2 * DIM);
    #pragma unroll
    for (int p = tid; p < 768; p += 512) {
        int e  = p * 2;
        int hh = e >> 7, d = e & 127;
        *(__half2*)(g_v + (((size_t)b * NH + hh) * NT + pos) * HD + d) = v2[p];
    }
}

// ------------------------- F16 flash attention (R10 config) ------------------
#define ATT_QS   0
#define ATT_K    52224
#define ATT_V    104448
#define ATT_PS   156672
#define SM_ATTN  184320

__global__ void __launch_bounds__(384, 1)
attn_kernel(void)
{
    extern __shared__ char smem[];
    const unsigned sb = smem_u32(smem);

    const int qt = blockIdx.x, h = blockIdx.y, b = blockIdx.z;
    const size_t base = (((size_t)b * NH + h) * NT) * HD;
    const __half* Qg = g_q + base + (size_t)qt * 192 * HD;
    const __half* Kg = g_k + base;
    const __half* Vg = g_v + base;

    const int tid  = threadIdx.x;
    const int lane = tid & 31;
    const int wid  = tid >> 5;
    const int l4   = lane >> 2;
    const int lm   = lane & 3;
    const int q0   = wid * 16;

    auto load_KV = [&](int kt, int slot) {
        unsigned kdst = sb + ATT_K + slot * 17408;
        unsigned vdst = sb + ATT_V + slot * 17408;
        const __half* ks = Kg + (size_t)kt * 64 * HD;
        const __half* vs = Vg + (size_t)kt * 64 * HD;
        for (int lin = tid; lin < 1024; lin += 384) {
            int row = lin >> 4, ch = lin & 15;
            cp16(kdst + row * 272 + ch * 16, ks + row * 128 + ch * 8);
            cp16(vdst + row * 272 + ch * 16, vs + row * 128 + ch * 8);
        }
    };

    for (int lin = tid; lin < 3072; lin += 384) {
        int row = lin >> 4, ch = lin & 15;
        cp16(sb + ATT_QS + row * 272 + ch * 16, Qg + row * 128 + ch * 8);
    }
    CP_COMMIT();
    load_KV(0, 0); CP_COMMIT();
    load_KV(1, 1); CP_COMMIT();

    float O[16][4];
    #pragma unroll
    for (int ni = 0; ni < 16; ni++)
        #pragma unroll
        for (int c = 0; c < 4; c++) O[ni][c] = 0.f;
    float m0 = -1e30f, m1 = -1e30f, l0 = 0.f, l1 = 0.f;

    const unsigned qa = sb + ATT_QS + (q0 + (lane & 15)) * 272 + (lane >> 4) * 16;
    const unsigned kb = (lane & 15) * 272 + (lane >> 4) * 16;
    const unsigned pa = sb + ATT_PS + (q0 + (lane & 15)) * 144 + (lane >> 4) * 16;
    const unsigned vtb = ((lane & 7) + ((lane >> 4) << 3)) * 272
                       + ((lane >> 3) & 1) * 16;

    for (int kt = 0; kt < NKT; kt++) {
        const int slot = kt % 3;
        CP_WAIT1();
        __syncthreads();
        if (kt + 2 < NKT) load_KV(kt + 2, (kt + 2) % 3);
        CP_COMMIT();

        const unsigned kbase = sb + ATT_K + slot * 17408 + kb;
        float s[8][4];
        #pragma unroll
        for (int ni = 0; ni < 8; ni++)
            #pragma unroll
            for (int c = 0; c < 4; c++) s[ni][c] = 0.f;

        #pragma unroll
        for (int kp = 0; kp < 8; kp++) {
            unsigned a[4];
            ldsm4(a, qa + kp * 32);
            #pragma unroll
            for (int nb = 0; nb < 4; nb++) {
                unsigned bf[4];
                ldsm4(bf, kbase + nb * 16 * 272 + kp * 32);
                mma16(s[2 * nb],     a, bf[0], bf[2]);
                mma16(s[2 * nb + 1], a, bf[1], bf[3]);
            }
        }

        float mx0 = -1e30f, mx1 = -1e30f;
        #pragma unroll
        for (int ni = 0; ni < 8; ni++) {
            mx0 = fmaxf(mx0, fmaxf(s[ni][0], s[ni][1]));
            mx1 = fmaxf(mx1, fmaxf(s[ni][2], s[ni][3]));
        }
        mx0 = fmaxf(mx0, __shfl_xor_sync(0xffffffffu, mx0, 1));
        mx0 = fmaxf(mx0, __shfl_xor_sync(0xffffffffu, mx0, 2));
        mx1 = fmaxf(mx1, __shfl_xor_sync(0xffffffffu, mx1, 1));
        mx1 = fmaxf(mx1, __shfl_xor_sync(0xffffffffu, mx1, 2));

        float mn0 = fmaxf(m0, mx0), mn1 = fmaxf(m1, mx1);
        float al0 = fexp(m0 - mn0), al1 = fexp(m1 - mn1);
        float ls0 = 0.f, ls1 = 0.f;
        #pragma unroll
        for (int ni = 0; ni < 8; ni++) {
            float p0 = fexp(s[ni][0] - mn0);
            float p1 = fexp(s[ni][1] - mn0);
            float p2 = fexp(s[ni][2] - mn1);
            float p3 = fexp(s[ni][3] - mn1);
            ls0 += p0 + p1; ls1 += p2 + p3;
            int cb = (ni * 8 + lm * 2) * 2;
            *(__half2*)(smem + ATT_PS + (q0 + l4) * 144 + cb) =
                __floats2half2_rn(p0, p1);
            *(__half2*)(smem + ATT_PS + (q0 + l4 + 8) * 144 + cb) =
                __floats2half2_rn(p2, p3);
        }
        ls0 += __shfl_xor_sync(0xffffffffu, ls0, 1);
        ls0 += __shfl_xor_sync(0xffffffffu, ls0, 2);
        ls1 += __shfl_xor_sync(0xffffffffu, ls1, 1);
        ls1 += __shfl_xor_sync(0xffffffffu, ls1, 2);
        l0 = l0 * al0 + ls0;  m0 = mn0;
        l1 = l1 * al1 + ls1;  m1 = mn1;
        #pragma unroll
        for (int ni = 0; ni < 16; ni++) {
            O[ni][0] *= al0; O[ni][1] *= al0;
            O[ni][2] *= al1; O[ni][3] *= al1;
        }
        __syncwarp();

        const unsigned vbase = sb + ATT_V + slot * 17408 + vtb;
        #pragma unroll
        for (int kp = 0; kp < 4; kp++) {
            unsigned a[4];
            ldsm4(a, pa + kp * 32);
            #pragma unroll
            for (int g = 0; g < 8; g++) {
                unsigned bf[4];
                ldsm4t(bf, vbase + kp * 16 * 272 + g * 32);
                mma16(O[2 * g],     a, bf[0], bf[2]);
                mma16(O[2 * g + 1], a, bf[1], bf[3]);
            }
        }
    }

    float inv0 = 1.0f / l0, inv1 = 1.0f / l1;
    size_t r0 = (size_t)qt * 192 + q0 + l4;
    __half* op0 = g_o + ((size_t)b * NT + r0) * DIM + h * HD;
    __half* op1 = g_o + ((size_t)b * NT + r0 + 8) * DIM + h * HD;
    #pragma unroll
    for (int ni = 0; ni < 16; ni++) {
        int cc = ni * 8 + lm * 2;
        *(__half2*)(op0 + cc) = __floats2half2_rn(O[ni][0] * inv0,
                                                  O[ni][1] * inv0);
        *(__half2*)(op1 + cc) = __floats2half2_rn(O[ni][2] * inv1,
                                                  O[ni][3] * inv1);
    }
}

// ------------------------- launch --------------------------------------------
extern "C" void kernel_launch(void* const* d_in, const int* in_sizes, int n_in,
                              void* d_out, int out_size)
{
    (void)in_sizes; (void)n_in; (void)out_size;

    const float* input     = (const float*)d_in[0];
    const float* context   = (const float*)d_in[1];
    const float* W_qkv_in  = (const float*)d_in[2];
    const float* b_qkv_in  = (const float*)d_in[3];
    const float* W_qkv_ctx = (const float*)d_in[4];
    const float* b_qkv_ctx = (const float*)d_in[5];
    const float* qs_in     = (const float*)d_in[6];
    const float* ks_in     = (const float*)d_in[7];
    const float* qs_ctx    = (const float*)d_in[8];
    const float* ks_ctx    = (const float*)d_in[9];
    const float* W_out_in  = (const float*)d_in[10];
    const float* b_out_in  = (const float*)d_in[11];
    const float* W_out_ctx = (const float*)d_in[12];
    const float* b_out_ctx = (const float*)d_in[13];
    float* out = (float*)d_out;

    cudaFuncSetAttribute(qkv_gemm,
                         cudaFuncAttributeMaxDynamicSharedMemorySize, SM_GEMM);
    cudaFuncSetAttribute(out_gemm,
                         cudaFuncAttributeMaxDynamicSharedMemorySize, SM_GEMM);
    cudaFuncSetAttribute(attn_kernel,
                         cudaFuncAttributeMaxDynamicSharedMemorySize, SM_ATTN);

    // 0) one prep launch: copies + rope + all weight transposes
    prep_kernel<<<dim3(6912, 1, 7), 256>>>(
        input, context, W_qkv_in, W_qkv_ctx, W_out_in, W_out_ctx);

    // 1) QKV projections
    qkv_gemm<<<dim3(Q3 / 128, 36), 256, SM_GEMM>>>(b_qkv_in, b_qkv_ctx);

    // 2) RMSNorm + RoPE + scatter (vectorized)
    normrope_kernel<<<dim3(NT, BB), 512>>>(qs_in, ks_in, qs_ctx, ks_ctx);

    // 3) Attention
    attn_kernel<<<dim3(NT / 192, NH, BB), 384, SM_ATTN>>>();

    // 4) Output projections
    out_gemm<<<dim3(DIM / 128, 36), 256, SM_GEMM>>>(b_out_in, b_out_ctx, out);
}

// round 17
// speedup vs baseline: 1.2319x; 1.0293x over previous
#include <cuda_runtime.h>
#include <cuda_fp16.h>
#include <math.h>
#include <stdint.h>

#define NH    12
#define HD    128
#define DIM   1536
#define BB    2
#define S_IN  2048
#define S_CTX 256
#define NT    (S_IN + S_CTX)   // 2304
#define Q3    (3 * DIM)        // 4608
#define NKT   (NT / 64)        // 36

// ------------------------- scratch (no cudaMalloc allowed) -------------------
static __device__ __half g_qkv_in [(size_t)BB * S_IN  * Q3];
static __device__ __half g_qkv_ctx[(size_t)BB * S_CTX * Q3];
static __device__ __half g_q[(size_t)BB * NH * NT * HD];   // scaled, [b][h][n][d]
static __device__ __half g_k[(size_t)BB * NH * NT * HD];   // [b][h][n][d]
static __device__ __half g_v[(size_t)BB * NH * NT * HD];   // [b][h][n][d]
static __device__ __half g_o[(size_t)BB * NT * DIM];
static __device__ __half g_wt[18874368];                   // transposed weights
static __device__ __half g_in_r [(size_t)BB * S_IN  * DIM];
static __device__ __half g_ctx_r[(size_t)BB * S_CTX * DIM];
static __device__ float2 g_rope[(size_t)NT * 64];          // (cos, sin)

#define WT_QKV_IN  0
#define WT_QKV_CTX 7077888
#define WT_OUT_IN  14155776
#define WT_OUT_CTX 16515072

// ------------------------- helpers -------------------------------------------
__device__ __forceinline__ unsigned smem_u32(const void* p) {
    unsigned a;
    asm("{ .reg .u64 t; cvta.to.shared.u64 t, %1; cvt.u32.u64 %0, t; }"
        : "=r"(a) : "l"(p));
    return a;
}

__device__ __forceinline__ void cp16(unsigned s, const void* g) {
    unsigned long long ga;
    asm("cvta.to.global.u64 %0, %1;" : "=l"(ga) : "l"(g));
    asm volatile("cp.async.cg.shared.global [%0], [%1], 16;"
                 :: "r"(s), "l"(ga));
}
#define CP_COMMIT() asm volatile("cp.async.commit_group;" ::: "memory")
#define CP_WAIT0()  asm volatile("cp.async.wait_group 0;" ::: "memory")
#define CP_WAIT1()  asm volatile("cp.async.wait_group 1;" ::: "memory")
#define CP_WAIT2()  asm volatile("cp.async.wait_group 2;" ::: "memory")

__device__ __forceinline__ void ldsm4(unsigned* r, unsigned addr) {
    asm volatile("ldmatrix.sync.aligned.m8n8.x4.shared.b16 {%0,%1,%2,%3}, [%4];"
        : "=r"(r[0]), "=r"(r[1]), "=r"(r[2]), "=r"(r[3]) : "r"(addr));
}

__device__ __forceinline__ void ldsm4t(unsigned* r, unsigned addr) {
    asm volatile("ldmatrix.sync.aligned.m8n8.x4.trans.shared.b16 {%0,%1,%2,%3}, [%4];"
        : "=r"(r[0]), "=r"(r[1]), "=r"(r[2]), "=r"(r[3]) : "r"(addr));
}

__device__ __forceinline__ void mma16(float* c, const unsigned* a,
                                      unsigned b0, unsigned b1) {
    asm volatile(
        "mma.sync.aligned.m16n8k16.row.col.f32.f16.f16.f32 "
        "{%0,%1,%2,%3}, {%4,%5,%6,%7}, {%8,%9}, {%0,%1,%2,%3};"
        : "+f"(c[0]), "+f"(c[1]), "+f"(c[2]), "+f"(c[3])
        : "r"(a[0]), "r"(a[1]), "r"(a[2]), "r"(a[3]), "r"(b0), "r"(b1));
}

__device__ __forceinline__ float fexp(float x) {
    float r;
    asm("ex2.approx.ftz.f32 %0, %1;" : "=f"(r) : "f"(x * 1.4426950408889634f));
    return r;
}

// pack two floats -> f16x2 register (bit reinterpret of __half2)
__device__ __forceinline__ unsigned packh2(float x, float y) {
    __half2 h = __floats2half2_rn(x, y);
    return *(unsigned*)&h;
}

// ------------------------- ONE merged prep kernel ----------------------------
__global__ void __launch_bounds__(256)
prep_kernel(const float* __restrict__ input, const float* __restrict__ context,
            const float* __restrict__ W0, const float* __restrict__ W1,
            const float* __restrict__ W2, const float* __restrict__ W3)
{
    const int z = blockIdx.z;
    if (z == 2) {                       // rope table
        int i = blockIdx.x * 256 + threadIdx.x;
        if (i < NT * 64) {
            int pos = i >> 6, t = i & 63;
            double ang = (double)pos * pow(10000.0, -(double)t / 64.0);
            g_rope[i] = make_float2((float)cos(ang), (float)sin(ang));
        }
        return;
    }
    if (z < 2) {                        // fp32 -> half copies
        const float* in = z ? context : input;
        __half* out     = z ? g_ctx_r : g_in_r;
        int n4          = (z ? BB * S_CTX * DIM : BB * S_IN * DIM) / 4;
        int i = blockIdx.x * 256 + threadIdx.x;
        if (i < n4) {
            float4 v = ((const float4*)in)[i];
            ((__half2*)out)[2 * i]     = __floats2half2_rn(v.x, v.y);
            ((__half2*)out)[2 * i + 1] = __floats2half2_rn(v.z, v.w);
        }
        return;
    }
    const float* W; size_t off; int N;
    switch (z) {
        case 3:  W = W0; off = WT_QKV_IN;  N = Q3;  break;
        case 4:  W = W1; off = WT_QKV_CTX; N = Q3;  break;
        case 5:  W = W2; off = WT_OUT_IN;  N = DIM; break;
        default: W = W3; off = WT_OUT_CTX; N = DIM; break;
    }
    const int nx = N / 32;
    const int bx = blockIdx.x % nx;
    const int by = blockIdx.x / nx;
    if (by >= DIM / 32) return;
    __half* Wt = g_wt + off;
    __shared__ float t[32][33];
    const int tx = threadIdx.x & 31, ty = threadIdx.x >> 5;
    int x  = bx * 32 + tx;
    int y0 = by * 32 + ty;
    #pragma unroll
    for (int j = 0; j < 4; j++)
        t[ty + j * 8][tx] = W[(size_t)(y0 + j * 8) * N + x];
    __syncthreads();
    int x2 = by * 32 + tx;
    int y2 = bx * 32 + ty;
    #pragma unroll
    for (int j = 0; j < 4; j++)
        Wt[(size_t)(y2 + j * 8) * DIM + x2] =
            __float2half_rn(t[tx][ty + j * 8]);
}

// ------------------------- F16 GEMM core (R10 config) ------------------------
#define G_STAGE 20480
#define SM_GEMM (4 * G_STAGE)

__device__ __forceinline__ void gstore(__half* p, float x, float y) {
    *(__half2*)p = __floats2half2_rn(x, y);
}
__device__ __forceinline__ void gstore(float* p, float x, float y) {
    *(float2*)p = make_float2(x, y);
}

template <typename OutT>
__device__ __forceinline__ void gemm_core(
    const __half* __restrict__ Ap, const __half* __restrict__ Wp,
    const float* __restrict__ bp, OutT* __restrict__ Cp,
    int K, int N, char* smem)
{
    const unsigned sb = smem_u32(smem);
    const int tid  = threadIdx.x;
    const int lane = tid & 31;
    const int wid  = tid >> 5;
    const int wm   = (wid & 1) * 64;
    const int wn   = (wid >> 1) * 32;
    const int l4   = lane >> 2;
    const int lm   = lane & 3;
    const int NCH  = K / 32;

    const int lrow = tid >> 1;
    const int lcb  = (tid & 1) * 32;
    auto issue = [&](int c, int st) {
        unsigned as = sb + st * G_STAGE;
        unsigned bs = as + 10240;
        const __half* ag = Ap + (size_t)lrow * K + c * 32 + lcb / 2;
        cp16(as + lrow * 80 + lcb, ag);
        cp16(as + lrow * 80 + lcb + 16, ag + 8);
        const __half* bg = Wp + (size_t)lrow * K + c * 32 + lcb / 2;
        cp16(bs + lrow * 80 + lcb, bg);
        cp16(bs + lrow * 80 + lcb + 16, bg + 8);
    };

    float acc[4][4][4];
    #pragma unroll
    for (int mi = 0; mi < 4; mi++)
        #pragma unroll
        for (int ni = 0; ni < 4; ni++)
            #pragma unroll
            for (int c = 0; c < 4; c++) acc[mi][ni][c] = 0.f;

    issue(0, 0); CP_COMMIT();
    issue(1, 1); CP_COMMIT();
    issue(2, 2); CP_COMMIT();

    const unsigned a_off = (wm + (lane & 15)) * 80 + (lane >> 4) * 16;
    const unsigned b_off = 10240 + (wn + (lane & 15)) * 80 + (lane >> 4) * 16;

    for (int i = 0; i < NCH; i++) {
        CP_WAIT2();
        __syncthreads();
        if (i + 3 < NCH) issue(i + 3, (i + 3) & 3);
        CP_COMMIT();

        unsigned st = sb + (i & 3) * G_STAGE;
        #pragma unroll
        for (int kp = 0; kp < 2; kp++) {
            unsigned af[4][4];
            #pragma unroll
            for (int mi = 0; mi < 4; mi++)
                ldsm4(af[mi], st + a_off + mi * 16 * 80 + kp * 32);
            #pragma unroll
            for (int nb = 0; nb < 2; nb++) {
                unsigned bf[4];
                ldsm4(bf, st + b_off + nb * 16 * 80 + kp * 32);
                #pragma unroll
                for (int mi = 0; mi < 4; mi++) {
                    mma16(acc[mi][2 * nb],     af[mi], bf[0], bf[2]);
                    mma16(acc[mi][2 * nb + 1], af[mi], bf[1], bf[3]);
                }
            }
        }
    }

    #pragma unroll
    for (int mi = 0; mi < 4; mi++) {
        #pragma unroll
        for (int ni = 0; ni < 4; ni++) {
            int r0 = wm + 16 * mi + l4;
            int c0 = wn + 8 * ni + 2 * lm;
            float bx = bp[c0], by = bp[c0 + 1];
            gstore(Cp + (size_t)r0 * N + c0,
                   acc[mi][ni][0] + bx, acc[mi][ni][1] + by);
            gstore(Cp + (size_t)(r0 + 8) * N + c0,
                   acc[mi][ni][2] + bx, acc[mi][ni][3] + by);
        }
    }
}

__global__ void __launch_bounds__(256, 2)
qkv_gemm(const float* __restrict__ b_in, const float* __restrict__ b_ctx)
{
    extern __shared__ char smem[];
    int y = blockIdx.y;
    const __half* A; const __half* W; const float* bias; __half* C;
    if (y < 32) {
        A = g_in_r + (size_t)y * 128 * DIM;
        W = g_wt + WT_QKV_IN;  bias = b_in;
        C = g_qkv_in + (size_t)y * 128 * Q3;
    } else {
        int y2 = y - 32;
        A = g_ctx_r + (size_t)y2 * 128 * DIM;
        W = g_wt + WT_QKV_CTX; bias = b_ctx;
        C = g_qkv_ctx + (size_t)y2 * 128 * Q3;
    }
    gemm_core<__half>(A, W + (size_t)blockIdx.x * 128 * DIM,
                      bias + blockIdx.x * 128, C + blockIdx.x * 128,
                      DIM, Q3, smem);
}

__global__ void __launch_bounds__(256, 2)
out_gemm(const float* __restrict__ b_in, const float* __restrict__ b_ctx,
         float* __restrict__ out)
{
    extern __shared__ char smem[];
    int y = blockIdx.y;
    const __half* A; const __half* W; const float* bias; float* C;
    if (y < 32) {
        int b = y >> 4, yy = y & 15;
        A = g_o + ((size_t)b * NT + S_CTX + yy * 128) * DIM;
        W = g_wt + WT_OUT_IN;  bias = b_in;
        C = out + ((size_t)b * S_IN + yy * 128) * DIM;
    } else {
        int z = y - 32, b = z >> 1, yy = z & 1;
        A = g_o + ((size_t)b * NT + yy * 128) * DIM;
        W = g_wt + WT_OUT_CTX; bias = b_ctx;
        C = out + (size_t)BB * S_IN * DIM + ((size_t)b * S_CTX + yy * 128) * DIM;
    }
    gemm_core<float>(A, W + (size_t)blockIdx.x * 128 * DIM,
                     bias + blockIdx.x * 128, C + blockIdx.x * 128,
                     DIM, DIM, smem);
}

// ----------------- RMSNorm + RoPE + scatter (vectorized half2) ---------------
__global__ void __launch_bounds__(512)
normrope_kernel(const float* __restrict__ qs_in, const float* __restrict__ ks_in,
                const float* __restrict__ qs_ctx, const float* __restrict__ ks_ctx)
{
    const int pos  = blockIdx.x;
    const int b    = blockIdx.y;
    const int tid  = threadIdx.x;
    const int half = tid >> 8;
    const int t    = tid & 255;

    __shared__ float2 buf[2][DIM / 2];
    __shared__ float  red[16];
    __shared__ float  cosv[64], sinv[64];

    const __half* src; const float* qs; const float* ks;
    if (pos < S_CTX) {
        src = g_qkv_ctx + ((size_t)b * S_CTX + pos) * Q3;
        qs = qs_ctx; ks = ks_ctx;
    } else {
        src = g_qkv_in + ((size_t)b * S_IN + (pos - S_CTX)) * Q3;
        qs = qs_in; ks = ks_in;
    }

    if (tid < 64) {
        float2 cs = g_rope[(size_t)pos * 64 + tid];
        cosv[tid] = cs.x;
        sinv[tid] = cs.y;
    }

    const float qscale = 0.088388347648318447f;

    const __half2* x2 = (const __half2*)(src + half * DIM);
    const float2*  s2 = (const float2*)(half ? ks : qs);
    float2 v[3];
    float local = 0.f;
    #pragma unroll
    for (int i = 0; i < 3; i++) {
        v[i] = __half22float2(x2[t + i * 256]);
        local = fmaf(v[i].x, v[i].x, fmaf(v[i].y, v[i].y, local));
    }
    #pragma unroll
    for (int off = 16; off; off >>= 1)
        local += __shfl_xor_sync(0xffffffffu, local, off);
    if ((tid & 31) == 0) red[tid >> 5] = local;
    __syncthreads();

    float tot = 0.f;
    #pragma unroll
    for (int j = 0; j < 8; j++) tot += red[half * 8 + j];
    float r = rsqrtf(tot * (1.0f / DIM) + 1e-6f);
    #pragma unroll
    for (int i = 0; i < 3; i++) {
        float2 sc = s2[t + i * 256];
        buf[half][t + i * 256] = make_float2(v[i].x * r * sc.x,
                                             v[i].y * r * sc.y);
    }
    __syncthreads();

    __half* dst = half ? g_k : g_q;
    float post = half ? 1.0f : qscale;
    #pragma unroll
    for (int i = 0; i < 3; i++) {
        int p  = t + i * 256;
        int e  = p * 2;
        int hh = e >> 7, d = e & 127;
        int j  = d & 63;
        float c0 = cosv[j],     sn0 = sinv[j];
        float c1 = cosv[j + 1], sn1 = sinv[j + 1];
        float2 a  = buf[half][p];
        float2 pr = buf[half][(d < 64) ? (p + 32) : (p - 32)];
        float y0, y1;
        if (d < 64) { y0 = a.x * c0 - pr.x * sn0; y1 = a.y * c1 - pr.y * sn1; }
        else        { y0 = a.x * c0 + pr.x * sn0; y1 = a.y * c1 + pr.y * sn1; }
        *(__half2*)(dst + (((size_t)b * NH + hh) * NT + pos) * HD + d) =
            __floats2half2_rn(y0 * post, y1 * post);
    }

    const __half2* v2 = (const __half2*)(src + 2 * DIM);
    #pragma unroll
    for (int p = tid; p < 768; p += 512) {
        int e  = p * 2;
        int hh = e >> 7, d = e & 127;
        *(__half2*)(g_v + (((size_t)b * NH + hh) * NT + pos) * HD + d) = v2[p];
    }
}

// ------------------------- F16 flash attention -------------------------------
// 192-query tile, 384 thr / 12 warps x 16q. K+V triple-buffered (one commit
// group per ktile). P stays IN REGISTERS: the S C-fragment layout equals the
// PV A-fragment layout (FA2 register path) -> no Ps smem, no STS/ldsm/syncwarp.
#define ATT_QS   0
#define ATT_K    52224
#define ATT_V    104448
#define SM_ATTN  156672

__global__ void __launch_bounds__(384, 1)
attn_kernel(void)
{
    extern __shared__ char smem[];
    const unsigned sb = smem_u32(smem);

    const int qt = blockIdx.x, h = blockIdx.y, b = blockIdx.z;
    const size_t base = (((size_t)b * NH + h) * NT) * HD;
    const __half* Qg = g_q + base + (size_t)qt * 192 * HD;
    const __half* Kg = g_k + base;
    const __half* Vg = g_v + base;

    const int tid  = threadIdx.x;
    const int lane = tid & 31;
    const int wid  = tid >> 5;
    const int lm   = lane & 3;
    const int l4   = lane >> 2;
    const int q0   = wid * 16;

    auto load_KV = [&](int kt, int slot) {
        unsigned kdst = sb + ATT_K + slot * 17408;
        unsigned vdst = sb + ATT_V + slot * 17408;
        const __half* ks = Kg + (size_t)kt * 64 * HD;
        const __half* vs = Vg + (size_t)kt * 64 * HD;
        for (int lin = tid; lin < 1024; lin += 384) {
            int row = lin >> 4, ch = lin & 15;
            cp16(kdst + row * 272 + ch * 16, ks + row * 128 + ch * 8);
            cp16(vdst + row * 272 + ch * 16, vs + row * 128 + ch * 8);
        }
    };

    for (int lin = tid; lin < 3072; lin += 384) {
        int row = lin >> 4, ch = lin & 15;
        cp16(sb + ATT_QS + row * 272 + ch * 16, Qg + row * 128 + ch * 8);
    }
    CP_COMMIT();
    load_KV(0, 0); CP_COMMIT();
    load_KV(1, 1); CP_COMMIT();

    float O[16][4];
    #pragma unroll
    for (int ni = 0; ni < 16; ni++)
        #pragma unroll
        for (int c = 0; c < 4; c++) O[ni][c] = 0.f;
    float m0 = -1e30f, m1 = -1e30f, l0 = 0.f, l1 = 0.f;

    const unsigned qa = sb + ATT_QS + (q0 + (lane & 15)) * 272 + (lane >> 4) * 16;
    const unsigned kb = (lane & 15) * 272 + (lane >> 4) * 16;
    const unsigned vtb = ((lane & 7) + ((lane >> 4) << 3)) * 272
                       + ((lane >> 3) & 1) * 16;

    #pragma unroll 3
    for (int kt = 0; kt < NKT; kt++) {
        const int slot = kt % 3;
        CP_WAIT1();
        __syncthreads();
        if (kt + 2 < NKT) load_KV(kt + 2, (kt + 2) % 3);
        CP_COMMIT();

        // ---- S = Q @ K^T ----
        const unsigned kbase = sb + ATT_K + slot * 17408 + kb;
        float s[8][4];
        #pragma unroll
        for (int ni = 0; ni < 8; ni++)
            #pragma unroll
            for (int c = 0; c < 4; c++) s[ni][c] = 0.f;

        #pragma unroll
        for (int kp = 0; kp < 8; kp++) {
            unsigned a[4];
            ldsm4(a, qa + kp * 32);
            #pragma unroll
            for (int nb = 0; nb < 4; nb++) {
                unsigned bf[4];
                ldsm4(bf, kbase + nb * 16 * 272 + kp * 32);
                mma16(s[2 * nb],     a, bf[0], bf[2]);
                mma16(s[2 * nb + 1], a, bf[1], bf[3]);
            }
        }

        // ---- online softmax (P stays in s[][]) ----
        float mx0 = -1e30f, mx1 = -1e30f;
        #pragma unroll
        for (int ni = 0; ni < 8; ni++) {
            mx0 = fmaxf(mx0, fmaxf(s[ni][0], s[ni][1]));
            mx1 = fmaxf(mx1, fmaxf(s[ni][2], s[ni][3]));
        }
        mx0 = fmaxf(mx0, __shfl_xor_sync(0xffffffffu, mx0, 1));
        mx0 = fmaxf(mx0, __shfl_xor_sync(0xffffffffu, mx0, 2));
        mx1 = fmaxf(mx1, __shfl_xor_sync(0xffffffffu, mx1, 1));
        mx1 = fmaxf(mx1, __shfl_xor_sync(0xffffffffu, mx1, 2));

        float mn0 = fmaxf(m0, mx0), mn1 = fmaxf(m1, mx1);
        float al0 = fexp(m0 - mn0), al1 = fexp(m1 - mn1);
        float ls0 = 0.f, ls1 = 0.f;
        #pragma unroll
        for (int ni = 0; ni < 8; ni++) {
            float p0 = fexp(s[ni][0] - mn0);
            float p1 = fexp(s[ni][1] - mn0);
            float p2 = fexp(s[ni][2] - mn1);
            float p3 = fexp(s[ni][3] - mn1);
            ls0 += p0 + p1; ls1 += p2 + p3;
            s[ni][0] = p0; s[ni][1] = p1; s[ni][2] = p2; s[ni][3] = p3;
        }
        ls0 += __shfl_xor_sync(0xffffffffu, ls0, 1);
        ls0 += __shfl_xor_sync(0xffffffffu, ls0, 2);
        ls1 += __shfl_xor_sync(0xffffffffu, ls1, 1);
        ls1 += __shfl_xor_sync(0xffffffffu, ls1, 2);
        l0 = l0 * al0 + ls0;  m0 = mn0;
        l1 = l1 * al1 + ls1;  m1 = mn1;
        #pragma unroll
        for (int ni = 0; ni < 16; ni++) {
            O[ni][0] *= al0; O[ni][1] *= al0;
            O[ni][2] *= al1; O[ni][3] *= al1;
        }

        // ---- O += P @ V : A-fragments built directly from s[][] ----
        const unsigned vbase = sb + ATT_V + slot * 17408 + vtb;
        #pragma unroll
        for (int kblk = 0; kblk < 4; kblk++) {
            unsigned a[4];
            a[0] = packh2(s[2 * kblk][0],     s[2 * kblk][1]);
            a[1] = packh2(s[2 * kblk][2],     s[2 * kblk][3]);
            a[2] = packh2(s[2 * kblk + 1][0], s[2 * kblk + 1][1]);
            a[3] = packh2(s[2 * kblk + 1][2], s[2 * kblk + 1][3]);
            #pragma unroll
            for (int g = 0; g < 8; g++) {
                unsigned bf[4];
                ldsm4t(bf, vbase + kblk * 16 * 272 + g * 32);
                mma16(O[2 * g],     a, bf[0], bf[2]);
                mma16(O[2 * g + 1], a, bf[1], bf[3]);
            }
        }
    }

    float inv0 = 1.0f / l0, inv1 = 1.0f / l1;
    size_t r0 = (size_t)qt * 192 + q0 + l4;
    __half* op0 = g_o + ((size_t)b * NT + r0) * DIM + h * HD;
    __half* op1 = g_o + ((size_t)b * NT + r0 + 8) * DIM + h * HD;
    #pragma unroll
    for (int ni = 0; ni < 16; ni++) {
        int cc = ni * 8 + lm * 2;
        *(__half2*)(op0 + cc) = __floats2half2_rn(O[ni][0] * inv0,
                                                  O[ni][1] * inv0);
        *(__half2*)(op1 + cc) = __floats2half2_rn(O[ni][2] * inv1,
                                                  O[ni][3] * inv1);
    }
}

// ------------------------- launch --------------------------------------------
extern "C" void kernel_launch(void* const* d_in, const int* in_sizes, int n_in,
                              void* d_out, int out_size)
{
    (void)in_sizes; (void)n_in; (void)out_size;

    const float* input     = (const float*)d_in[0];
    const float* context   = (const float*)d_in[1];
    const float* W_qkv_in  = (const float*)d_in[2];
    const float* b_qkv_in  = (const float*)d_in[3];
    const float* W_qkv_ctx = (const float*)d_in[4];
    const float* b_qkv_ctx = (const float*)d_in[5];
    const float* qs_in     = (const float*)d_in[6];
    const float* ks_in     = (const float*)d_in[7];
    const float* qs_ctx    = (const float*)d_in[8];
    const float* ks_ctx    = (const float*)d_in[9];
    const float* W_out_in  = (const float*)d_in[10];
    const float* b_out_in  = (const float*)d_in[11];
    const float* W_out_ctx = (const float*)d_in[12];
    const float* b_out_ctx = (const float*)d_in[13];
    float* out = (float*)d_out;

    cudaFuncSetAttribute(qkv_gemm,
                         cudaFuncAttributeMaxDynamicSharedMemorySize, SM_GEMM);
    cudaFuncSetAttribute(out_gemm,
                         cudaFuncAttributeMaxDynamicSharedMemorySize, SM_GEMM);
    cudaFuncSetAttribute(attn_kernel,
                         cudaFuncAttributeMaxDynamicSharedMemorySize, SM_ATTN);

    prep_kernel<<<dim3(6912, 1, 7), 256>>>(
        input, context, W_qkv_in, W_qkv_ctx, W_out_in, W_out_ctx);

    qkv_gemm<<<dim3(Q3 / 128, 36), 256, SM_GEMM>>>(b_qkv_in, b_qkv_ctx);

    normrope_kernel<<<dim3(NT, BB), 512>>>(qs_in, ks_in, qs_ctx, ks_ctx);

    attn_kernel<<<dim3(NT / 192, NH, BB), 384, SM_ATTN>>>();

    out_gemm<<<dim3(DIM / 128, 36), 256, SM_GEMM>>>(b_out_in, b_out_ctx, out);
}